// round 1
// baseline (speedup 1.0000x reference)
#include <cuda_runtime.h>
#include <math.h>

#define MTOT 8192
#define KDIM 8192
#define DIM 128
#define FEAT 256
#define EPSV 1e-5f
#define STATS_BLOCKS 64

// ---------------- scratch (device globals; no allocs allowed) ----------------
__device__ float g_bufX [MTOT * DIM];   // activations entering a block
__device__ float g_bufX2[MTOT * DIM];   // activations entering block 2
__device__ float g_bufLx[MTOT * DIM];   // L @ x
__device__ float g_partials[STATS_BLOCKS * 4 * DIM];
__device__ float g_scale[FEAT];
__device__ float g_shift[FEAT];
__device__ float g_wT[FEAT * DIM];      // transposed effective weight
__device__ float g_beff[DIM];

// ---------------- ELU of the network input ----------------
__global__ __launch_bounds__(256) void elu_kernel(const float* __restrict__ in) {
    int i = blockIdx.x * blockDim.x + threadIdx.x;  // over float4, 262144 total
    float4 v = ((const float4*)in)[i];
    v.x = v.x > 0.f ? v.x : expm1f(v.x);
    v.y = v.y > 0.f ? v.y : expm1f(v.y);
    v.z = v.z > 0.f ? v.z : expm1f(v.z);
    v.w = v.w > 0.f ? v.w : expm1f(v.w);
    ((float4*)g_bufX)[i] = v;
}

// ---------------- big GEMM: g_bufLx = L @ X  (8192x8192 @ 8192x128) ----------
// BM=64, BN=128, BK=16, 256 threads, per-thread 4x8 tile, double-buffered smem.
__global__ __launch_bounds__(256) void sgemm_kernel(const float* __restrict__ A, int xsel) {
    __shared__ float As[2][16][68];   // padded (272B rows, 16B aligned)
    __shared__ float Bs[2][16][128];

    const float* __restrict__ B = xsel ? g_bufX2 : g_bufX;
    float* __restrict__ C = g_bufLx;

    const int tid  = threadIdx.x;
    const int m0   = blockIdx.x * 64;
    const int rowA = tid >> 2;          // 0..63
    const int colA = (tid & 3) << 2;    // 0,4,8,12
    const int rowB = tid >> 4;          // 0..15
    const int colB = (tid & 15) << 3;   // 0..120
    const int ty   = tid >> 4;          // 0..15
    const int tx   = tid & 15;          // 0..15

    const float* Ap = A + (size_t)(m0 + rowA) * KDIM + colA;
    const float* Bp = B + rowB * DIM + colB;

    float acc[4][8];
#pragma unroll
    for (int i = 0; i < 4; i++)
#pragma unroll
        for (int j = 0; j < 8; j++) acc[i][j] = 0.f;

    // prologue: tile 0
    {
        float4 a  = *(const float4*)Ap;
        float4 b0 = *(const float4*)Bp;
        float4 b1 = *(const float4*)(Bp + 4);
        As[0][colA + 0][rowA] = a.x;
        As[0][colA + 1][rowA] = a.y;
        As[0][colA + 2][rowA] = a.z;
        As[0][colA + 3][rowA] = a.w;
        *(float4*)&Bs[0][rowB][colB]     = b0;
        *(float4*)&Bs[0][rowB][colB + 4] = b1;
    }

    int buf = 0;
    const int T = KDIM / 16;  // 512
    for (int t = 0; t < T; ++t) {
        __syncthreads();
        float4 na, nb0, nb1;
        const bool more = (t + 1) < T;
        if (more) {
            na = *(const float4*)(Ap + (size_t)(t + 1) * 16);
            const float* bp = Bp + (size_t)(t + 1) * 16 * DIM;
            nb0 = *(const float4*)bp;
            nb1 = *(const float4*)(bp + 4);
        }
#pragma unroll
        for (int k = 0; k < 16; k++) {
            float4 av  = *(const float4*)&As[buf][k][ty << 2];
            float4 bvA = *(const float4*)&Bs[buf][k][tx << 3];
            float4 bvB = *(const float4*)&Bs[buf][k][(tx << 3) + 4];
            float ar[4] = {av.x, av.y, av.z, av.w};
            float br[8] = {bvA.x, bvA.y, bvA.z, bvA.w, bvB.x, bvB.y, bvB.z, bvB.w};
#pragma unroll
            for (int i = 0; i < 4; i++)
#pragma unroll
                for (int j = 0; j < 8; j++) acc[i][j] = fmaf(ar[i], br[j], acc[i][j]);
        }
        if (more) {
            int nb = buf ^ 1;
            As[nb][colA + 0][rowA] = na.x;
            As[nb][colA + 1][rowA] = na.y;
            As[nb][colA + 2][rowA] = na.z;
            As[nb][colA + 3][rowA] = na.w;
            *(float4*)&Bs[nb][rowB][colB]     = nb0;
            *(float4*)&Bs[nb][rowB][colB + 4] = nb1;
            buf = nb;
        }
    }

    float* Cp = C + (size_t)(m0 + (ty << 2)) * DIM + (tx << 3);
#pragma unroll
    for (int i = 0; i < 4; i++) {
        *(float4*)(Cp + (size_t)i * DIM)     = make_float4(acc[i][0], acc[i][1], acc[i][2], acc[i][3]);
        *(float4*)(Cp + (size_t)i * DIM + 4) = make_float4(acc[i][4], acc[i][5], acc[i][6], acc[i][7]);
    }
}

// ---------------- BN stats pass 1: per-block partial sum/sumsq --------------
__global__ __launch_bounds__(256) void stats_partial(int xsel) {
    const float* __restrict__ X  = xsel ? g_bufX2 : g_bufX;
    const float* __restrict__ LX = g_bufLx;
    const int tid  = threadIdx.x;
    const int c    = tid & 127;
    const int half = tid >> 7;
    const int rpb  = MTOT / STATS_BLOCKS;  // 128
    const int r0   = blockIdx.x * rpb;

    float sx = 0.f, sxx = 0.f, sl = 0.f, sll = 0.f;
    for (int r = r0 + half; r < r0 + rpb; r += 2) {
        float v = X[r * DIM + c];
        sx += v; sxx += v * v;
        float w = LX[r * DIM + c];
        sl += w; sll += w * w;
    }
    __shared__ float sh[256];
    sh[tid] = sx;  __syncthreads();
    if (tid < 128) g_partials[blockIdx.x * 512 + 0 * 128 + c] = sh[tid] + sh[tid + 128];
    __syncthreads();
    sh[tid] = sxx; __syncthreads();
    if (tid < 128) g_partials[blockIdx.x * 512 + 1 * 128 + c] = sh[tid] + sh[tid + 128];
    __syncthreads();
    sh[tid] = sl;  __syncthreads();
    if (tid < 128) g_partials[blockIdx.x * 512 + 2 * 128 + c] = sh[tid] + sh[tid + 128];
    __syncthreads();
    sh[tid] = sll; __syncthreads();
    if (tid < 128) g_partials[blockIdx.x * 512 + 3 * 128 + c] = sh[tid] + sh[tid + 128];
}

// ---------------- BN stats pass 2: mean/var -> scale/shift ------------------
__global__ void stats_final(const float* __restrict__ gamma, const float* __restrict__ beta) {
    int k = threadIdx.x;                 // 0..255 feature of h = [x | Lx]
    int base = (k < 128) ? 0 : 2;
    int c = k & 127;
    float s = 0.f, ss = 0.f;
    for (int b = 0; b < STATS_BLOCKS; b++) {
        s  += g_partials[b * 512 + base * 128 + c];
        ss += g_partials[b * 512 + (base + 1) * 128 + c];
    }
    float mean = s / (float)MTOT;
    float var  = ss / (float)MTOT - mean * mean;
    float sc   = rsqrtf(var + EPSV) * gamma[k];
    g_scale[k] = sc;
    g_shift[k] = beta[k] - mean * sc;
}

// ---------------- fold BN into linear weights -------------------------------
// wT[k][j] = w[j][k]*scale[k];  beff[j] = b[j] + sum_k shift[k]*w[j][k]
__global__ void weff_kernel(const float* __restrict__ w, const float* __restrict__ b) {
    int tid = threadIdx.x;  // 256 = k
    float sc = g_scale[tid];
    for (int j = 0; j < 128; j++)
        g_wT[tid * 128 + j] = w[j * 256 + tid] * sc;
    if (tid < 128) {
        float s = b[tid];
        for (int k = 0; k < 256; k++)
            s += g_shift[k] * w[tid * 256 + k];
        g_beff[tid] = s;
    }
}

// ---------------- small GEMM: [X|LX](8192x256) @ wT(256x128) + epilogue -----
// mode 0: out = elu(y)  -> g_bufX2 ; mode 1: out = y + resid -> dst
__global__ __launch_bounds__(256) void linear_kernel(int xsel,
                                                     const float* __restrict__ resid,
                                                     float* __restrict__ dst, int mode) {
    __shared__ float As[2][16][68];
    __shared__ float Bs[2][16][128];

    const float* __restrict__ X  = xsel ? g_bufX2 : g_bufX;
    const float* __restrict__ LX = g_bufLx;

    const int tid  = threadIdx.x;
    const int m0   = blockIdx.x * 64;
    const int rowA = tid >> 2;
    const int colA = (tid & 3) << 2;
    const int rowB = tid >> 4;
    const int colB = (tid & 15) << 3;
    const int ty   = tid >> 4;
    const int tx   = tid & 15;

    float acc[4][8];
#pragma unroll
    for (int i = 0; i < 4; i++)
#pragma unroll
        for (int j = 0; j < 8; j++) acc[i][j] = 0.f;

    const int T = FEAT / 16;  // 16

    // prologue: tile 0 (kk < 128 -> X)
    {
        const float* s = X + (size_t)(m0 + rowA) * DIM + colA;
        float4 a = *(const float4*)s;
        As[0][colA + 0][rowA] = a.x;
        As[0][colA + 1][rowA] = a.y;
        As[0][colA + 2][rowA] = a.z;
        As[0][colA + 3][rowA] = a.w;
        const float* bp = g_wT + rowB * DIM + colB;
        *(float4*)&Bs[0][rowB][colB]     = *(const float4*)bp;
        *(float4*)&Bs[0][rowB][colB + 4] = *(const float4*)(bp + 4);
    }

    int buf = 0;
    for (int t = 0; t < T; ++t) {
        __syncthreads();
        float4 na, nb0, nb1;
        const bool more = (t + 1) < T;
        if (more) {
            int kk = (t + 1) * 16 + colA;
            const float* s = (kk < 128) ? (X  + (size_t)(m0 + rowA) * DIM + kk)
                                        : (LX + (size_t)(m0 + rowA) * DIM + (kk - 128));
            na = *(const float4*)s;
            const float* bp = g_wT + (size_t)((t + 1) * 16 + rowB) * DIM + colB;
            nb0 = *(const float4*)bp;
            nb1 = *(const float4*)(bp + 4);
        }
#pragma unroll
        for (int k = 0; k < 16; k++) {
            float4 av  = *(const float4*)&As[buf][k][ty << 2];
            float4 bvA = *(const float4*)&Bs[buf][k][tx << 3];
            float4 bvB = *(const float4*)&Bs[buf][k][(tx << 3) + 4];
            float ar[4] = {av.x, av.y, av.z, av.w};
            float br[8] = {bvA.x, bvA.y, bvA.z, bvA.w, bvB.x, bvB.y, bvB.z, bvB.w};
#pragma unroll
            for (int i = 0; i < 4; i++)
#pragma unroll
                for (int j = 0; j < 8; j++) acc[i][j] = fmaf(ar[i], br[j], acc[i][j]);
        }
        if (more) {
            int nb = buf ^ 1;
            As[nb][colA + 0][rowA] = na.x;
            As[nb][colA + 1][rowA] = na.y;
            As[nb][colA + 2][rowA] = na.z;
            As[nb][colA + 3][rowA] = na.w;
            *(float4*)&Bs[nb][rowB][colB]     = nb0;
            *(float4*)&Bs[nb][rowB][colB + 4] = nb1;
            buf = nb;
        }
    }

    float* o = (mode == 0) ? g_bufX2 : dst;
    const int row = m0 + (ty << 2);
    const int col = tx << 3;
#pragma unroll
    for (int i = 0; i < 4; i++) {
        float yv[8];
#pragma unroll
        for (int j = 0; j < 8; j++) {
            float y = acc[i][j] + g_beff[col + j];
            if (mode == 0) {
                yv[j] = y > 0.f ? y : expm1f(y);
            } else {
                yv[j] = y + resid[(size_t)(row + i) * DIM + col + j];
            }
        }
        *(float4*)(o + (size_t)(row + i) * DIM + col)     = make_float4(yv[0], yv[1], yv[2], yv[3]);
        *(float4*)(o + (size_t)(row + i) * DIM + col + 4) = make_float4(yv[4], yv[5], yv[6], yv[7]);
    }
}

// ---------------- launch ----------------------------------------------------
extern "C" void kernel_launch(void* const* d_in, const int* in_sizes, int n_in,
                              void* d_out, int out_size) {
    const float* L      = (const float*)d_in[0];
    // d_in[1] = mask (unused in forward)
    const float* inputs = (const float*)d_in[2];
    const float* bn0_g  = (const float*)d_in[3];
    const float* bn0_b  = (const float*)d_in[4];
    const float* fc0_w  = (const float*)d_in[5];
    const float* fc0_b  = (const float*)d_in[6];
    const float* bn1_g  = (const float*)d_in[7];
    const float* bn1_b  = (const float*)d_in[8];
    const float* fc1_w  = (const float*)d_in[9];
    const float* fc1_b  = (const float*)d_in[10];
    float* out = (float*)d_out;

    // x = elu(inputs)
    elu_kernel<<<(MTOT * DIM / 4) / 256, 256>>>(inputs);

    // ---- block 0 ----
    sgemm_kernel<<<MTOT / 64, 256>>>(L, 0);           // Lx = L @ x
    stats_partial<<<STATS_BLOCKS, 256>>>(0);
    stats_final<<<1, 256>>>(bn0_g, bn0_b);
    weff_kernel<<<1, 256>>>(fc0_w, fc0_b);
    linear_kernel<<<MTOT / 64, 256>>>(0, nullptr, nullptr, 0);  // x2 = elu(BN->fc0)

    // ---- block 1 ----
    sgemm_kernel<<<MTOT / 64, 256>>>(L, 1);           // Lx = L @ x2
    stats_partial<<<STATS_BLOCKS, 256>>>(1);
    stats_final<<<1, 256>>>(bn1_g, bn1_b);
    weff_kernel<<<1, 256>>>(fc1_w, fc1_b);
    linear_kernel<<<MTOT / 64, 256>>>(1, inputs, out, 1);       // out = fc1 + inputs
}

// round 3
// speedup vs baseline: 2.9642x; 2.9642x over previous
#include <cuda_runtime.h>
#include <cuda_bf16.h>
#include <math.h>
#include <stdint.h>

#define MTOT 8192
#define KDIM 8192
#define DIM 128
#define FEAT 256
#define EPSV 1e-5f
#define STATS_BLOCKS 64

// ---------------- scratch (device globals; no allocs allowed) ----------------
__device__ float g_bufX [MTOT * DIM];   // activations entering a block (fp32)
__device__ float g_bufX2[MTOT * DIM];   // activations entering block 2 (fp32)
__device__ float g_Lx0  [MTOT * DIM];   // partial L@x, K slice 0
__device__ float g_Lx1  [MTOT * DIM];   // partial L@x, K slice 1
// B^T operand, bf16 hi/lo: row-major [feat 128][node 8192]
__device__ __nv_bfloat16 g_Bh[DIM * MTOT];
__device__ __nv_bfloat16 g_Bl[DIM * MTOT];
__device__ float g_partials[STATS_BLOCKS * 4 * DIM];
__device__ float g_scale[FEAT];
__device__ float g_shift[FEAT];
__device__ float g_wT[FEAT * DIM];
__device__ float g_beff[DIM];

// ---------------- helpers ----------------
__device__ __forceinline__ uint32_t smem_u32(const void* p) {
    uint32_t a;
    asm("{ .reg .u64 t; cvta.to.shared.u64 t, %1; cvt.u32.u64 %0, t; }" : "=r"(a) : "l"(p));
    return a;
}
__device__ __forceinline__ void ldmx4(uint32_t* r, uint32_t addr) {
    asm volatile("ldmatrix.sync.aligned.m8n8.x4.shared.b16 {%0,%1,%2,%3}, [%4];"
                 : "=r"(r[0]), "=r"(r[1]), "=r"(r[2]), "=r"(r[3]) : "r"(addr));
}
__device__ __forceinline__ void mma_bf16(float* d, const uint32_t* a, uint32_t b0, uint32_t b1) {
    asm volatile(
        "mma.sync.aligned.m16n8k16.row.col.f32.bf16.bf16.f32 "
        "{%0,%1,%2,%3}, {%4,%5,%6,%7}, {%8,%9}, {%0,%1,%2,%3};"
        : "+f"(d[0]), "+f"(d[1]), "+f"(d[2]), "+f"(d[3])
        : "r"(a[0]), "r"(a[1]), "r"(a[2]), "r"(a[3]), "r"(b0), "r"(b1));
}

// ---------------- ELU of the network input ----------------
__global__ __launch_bounds__(256) void elu_kernel(const float* __restrict__ in) {
    int i = blockIdx.x * blockDim.x + threadIdx.x;
    float4 v = ((const float4*)in)[i];
    v.x = v.x > 0.f ? v.x : expm1f(v.x);
    v.y = v.y > 0.f ? v.y : expm1f(v.y);
    v.z = v.z > 0.f ? v.z : expm1f(v.z);
    v.w = v.w > 0.f ? v.w : expm1f(v.w);
    ((float4*)g_bufX)[i] = v;
}

// ---------------- pack: X (node-major fp32) -> B^T (feat-major bf16 hi/lo) --
// grid 128 blocks, each handles 64 nodes x 128 feats; smem transpose.
__global__ __launch_bounds__(256) void pack_kernel(int xsel) {
    const float* __restrict__ src = xsel ? g_bufX2 : g_bufX;
    __shared__ float tile[128][65];   // [feat][node_local]
    const int tid = threadIdx.x;
    const int node0 = blockIdx.x * 64;

    const float4* sv = (const float4*)src + (size_t)node0 * 32;
#pragma unroll
    for (int i = 0; i < 8; i++) {
        int idx = tid + 256 * i;          // float4 index within 64x128 tile
        int node = idx >> 5;              // 0..63
        int fq = idx & 31;                // float4 within row
        float4 v = sv[idx];
        tile[fq * 4 + 0][node] = v.x;
        tile[fq * 4 + 1][node] = v.y;
        tile[fq * 4 + 2][node] = v.z;
        tile[fq * 4 + 3][node] = v.w;
    }
    __syncthreads();

    const int feat = tid >> 1;
    const int h = tid & 1;                // 32-node half
    const float* r = &tile[feat][h * 32];
    uint32_t hi[16], lo[16];
#pragma unroll
    for (int j = 0; j < 16; j++) {
        float a = r[2 * j], b = r[2 * j + 1];
        __nv_bfloat162 hb = __floats2bfloat162_rn(a, b);
        float ha = __low2float(hb), hbv = __high2float(hb);
        __nv_bfloat162 lb = __floats2bfloat162_rn(a - ha, b - hbv);
        hi[j] = *(uint32_t*)&hb;
        lo[j] = *(uint32_t*)&lb;
    }
    uint4* oh = (uint4*)(g_Bh + (size_t)feat * MTOT + node0 + h * 32);
    uint4* ol = (uint4*)(g_Bl + (size_t)feat * MTOT + node0 + h * 32);
#pragma unroll
    for (int blk = 0; blk < 4; blk++) {
        oh[blk] = make_uint4(hi[4 * blk], hi[4 * blk + 1], hi[4 * blk + 2], hi[4 * blk + 3]);
        ol[blk] = make_uint4(lo[4 * blk], lo[4 * blk + 1], lo[4 * blk + 2], lo[4 * blk + 3]);
    }
}

// ---------------- split-bf16 HMMA GEMM: Lx_partial = L[:,slice] @ X[slice] --
// 128 CTAs = 64 M-tiles x 2 K-slices. CTA: M=128,N=128,BK=32,K=4096.
// smem per stage: Ah|Al|Bh|Bl each 128 rows x 40 halfs (80B) = 10240B -> 40960B
#define ROWB 80
#define OPSZ 10240
#define STGSZ 40960
#define SGEMM_SMEM (2 * STGSZ)

__global__ __launch_bounds__(256, 1) void sgemm_mma(const float* __restrict__ L) {
    extern __shared__ char smem[];
    const int tid = threadIdx.x;
    const int lane = tid & 31;
    const int w = tid >> 5;
    const int wm = w >> 1;                 // 0..3 : M 32-row band
    const int wn = w & 1;                  // 0..1 : N 64-col band
    const int mtile = blockIdx.x >> 1;
    const int ksl = blockIdx.x & 1;
    const int m0 = mtile * 128;
    const int kc0 = ksl * 4096;

    const uint32_t sb = smem_u32(smem);

    // ldmatrix per-lane offsets (bytes within an operand block)
    const int a_row = wm * 32 + (lane & 7) + ((lane >> 3) & 1) * 8;
    const uint32_t aOff = (uint32_t)a_row * ROWB + ((lane >> 4) & 1) * 16;
    const int b_row = wn * 64 + (lane & 7) + ((lane >> 4) & 1) * 8;
    const uint32_t bOff = (uint32_t)b_row * ROWB + ((lane >> 3) & 1) * 16;

    // global load assignment
    const int grow = tid >> 1;             // 0..127
    const int gh = tid & 1;                // k half (16 elems)
    const float* Ap = L + (size_t)(m0 + grow) * KDIM + kc0 + gh * 16;
    const __nv_bfloat16* Bhp = g_Bh + (size_t)grow * MTOT + kc0 + gh * 16;
    const __nv_bfloat16* Blp = g_Bl + (size_t)grow * MTOT + kc0 + gh * 16;
    const uint32_t aStOff = (uint32_t)grow * ROWB + gh * 32;  // bytes
    const uint32_t bStOff = aStOff;

    float acc[2][8][4];
#pragma unroll
    for (int i = 0; i < 2; i++)
#pragma unroll
        for (int j = 0; j < 8; j++)
#pragma unroll
            for (int q = 0; q < 4; q++) acc[i][j][q] = 0.f;

    float4 ar[4];
    uint4 brh[2], brl[2];

    // prologue: load tile 0 and store to stage 0
#pragma unroll
    for (int i = 0; i < 4; i++) ar[i] = *(const float4*)(Ap + 4 * i);
    brh[0] = ((const uint4*)Bhp)[0]; brh[1] = ((const uint4*)Bhp)[1];
    brl[0] = ((const uint4*)Blp)[0]; brl[1] = ((const uint4*)Blp)[1];
    {
        char* sAh = smem + aStOff;
        char* sAl = smem + OPSZ + aStOff;
#pragma unroll
        for (int i = 0; i < 4; i++) {
            float4 v = ar[i];
            __nv_bfloat162 h01 = __floats2bfloat162_rn(v.x, v.y);
            __nv_bfloat162 h23 = __floats2bfloat162_rn(v.z, v.w);
            __nv_bfloat162 l01 = __floats2bfloat162_rn(v.x - __low2float(h01), v.y - __high2float(h01));
            __nv_bfloat162 l23 = __floats2bfloat162_rn(v.z - __low2float(h23), v.w - __high2float(h23));
            *(uint2*)(sAh + 8 * i) = make_uint2(*(uint32_t*)&h01, *(uint32_t*)&h23);
            *(uint2*)(sAl + 8 * i) = make_uint2(*(uint32_t*)&l01, *(uint32_t*)&l23);
        }
        *(uint4*)(smem + 2 * OPSZ + bStOff)      = brh[0];
        *(uint4*)(smem + 2 * OPSZ + bStOff + 16) = brh[1];
        *(uint4*)(smem + 3 * OPSZ + bStOff)      = brl[0];
        *(uint4*)(smem + 3 * OPSZ + bStOff + 16) = brl[1];
    }

    const int T = 4096 / 32;  // 128
    uint32_t stageBase = sb;

    for (int t = 0; t < T; t++) {
        __syncthreads();
        const bool more = (t + 1) < T;
        if (more) {
            const int off = (t + 1) * 32;
#pragma unroll
            for (int i = 0; i < 4; i++) ar[i] = *(const float4*)(Ap + off + 4 * i);
            const uint4* bh = (const uint4*)(Bhp + off);
            const uint4* bl = (const uint4*)(Blp + off);
            brh[0] = bh[0]; brh[1] = bh[1];
            brl[0] = bl[0]; brl[1] = bl[1];
        }

        // ---- compute from current stage ----
        const uint32_t sA = stageBase;
#pragma unroll
        for (int ks = 0; ks < 2; ks++) {
            const uint32_t kb = ks * 32;  // 16 halfs
            uint32_t Ah[2][4], Al[2][4], Bh[4][4], Bl[4][4];
#pragma unroll
            for (int mf = 0; mf < 2; mf++) {
                ldmx4(Ah[mf], sA + aOff + mf * (16 * ROWB) + kb);
                ldmx4(Al[mf], sA + OPSZ + aOff + mf * (16 * ROWB) + kb);
            }
#pragma unroll
            for (int q = 0; q < 4; q++) {
                ldmx4(Bh[q], sA + 2 * OPSZ + bOff + q * (16 * ROWB) + kb);
                ldmx4(Bl[q], sA + 3 * OPSZ + bOff + q * (16 * ROWB) + kb);
            }
#pragma unroll
            for (int mf = 0; mf < 2; mf++)
#pragma unroll
                for (int nf = 0; nf < 8; nf++) {
                    const int q = nf >> 1, rr = (nf & 1) * 2;
                    mma_bf16(acc[mf][nf], Ah[mf], Bh[q][rr], Bh[q][rr + 1]);
                    mma_bf16(acc[mf][nf], Ah[mf], Bl[q][rr], Bl[q][rr + 1]);
                    mma_bf16(acc[mf][nf], Al[mf], Bh[q][rr], Bh[q][rr + 1]);
                }
        }

        // ---- store next tile into other stage ----
        if (more) {
            char* other = smem + (((t & 1) == 0) ? STGSZ : 0);
            char* sAh = other + aStOff;
            char* sAl = other + OPSZ + aStOff;
#pragma unroll
            for (int i = 0; i < 4; i++) {
                float4 v = ar[i];
                __nv_bfloat162 h01 = __floats2bfloat162_rn(v.x, v.y);
                __nv_bfloat162 h23 = __floats2bfloat162_rn(v.z, v.w);
                __nv_bfloat162 l01 = __floats2bfloat162_rn(v.x - __low2float(h01), v.y - __high2float(h01));
                __nv_bfloat162 l23 = __floats2bfloat162_rn(v.z - __low2float(h23), v.w - __high2float(h23));
                *(uint2*)(sAh + 8 * i) = make_uint2(*(uint32_t*)&h01, *(uint32_t*)&h23);
                *(uint2*)(sAl + 8 * i) = make_uint2(*(uint32_t*)&l01, *(uint32_t*)&l23);
            }
            *(uint4*)(other + 2 * OPSZ + bStOff)      = brh[0];
            *(uint4*)(other + 2 * OPSZ + bStOff + 16) = brh[1];
            *(uint4*)(other + 3 * OPSZ + bStOff)      = brl[0];
            *(uint4*)(other + 3 * OPSZ + bStOff + 16) = brl[1];
            stageBase = sb + (((t & 1) == 0) ? STGSZ : 0);
        }
    }

    // ---- epilogue: write fp32 partials ----
    float* outb = ksl ? g_Lx1 : g_Lx0;
    const int g = lane >> 2, t4 = lane & 3;
#pragma unroll
    for (int mf = 0; mf < 2; mf++) {
        const int row0 = m0 + wm * 32 + mf * 16 + g;
#pragma unroll
        for (int nf = 0; nf < 8; nf++) {
            const int col = wn * 64 + nf * 8 + t4 * 2;
            *(float2*)(outb + (size_t)row0 * DIM + col) =
                make_float2(acc[mf][nf][0], acc[mf][nf][1]);
            *(float2*)(outb + (size_t)(row0 + 8) * DIM + col) =
                make_float2(acc[mf][nf][2], acc[mf][nf][3]);
        }
    }
}

// ---------------- BN stats pass 1 -------------------------------------------
__global__ __launch_bounds__(256) void stats_partial(int xsel) {
    const float* __restrict__ X = xsel ? g_bufX2 : g_bufX;
    const int tid = threadIdx.x;
    const int c = tid & 127;
    const int half = tid >> 7;
    const int rpb = MTOT / STATS_BLOCKS;
    const int r0 = blockIdx.x * rpb;

    float sx = 0.f, sxx = 0.f, sl = 0.f, sll = 0.f;
    for (int r = r0 + half; r < r0 + rpb; r += 2) {
        float v = X[r * DIM + c];
        sx += v; sxx += v * v;
        float w = g_Lx0[r * DIM + c] + g_Lx1[r * DIM + c];
        sl += w; sll += w * w;
    }
    __shared__ float sh[256];
    sh[tid] = sx;  __syncthreads();
    if (tid < 128) g_partials[blockIdx.x * 512 + 0 * 128 + c] = sh[tid] + sh[tid + 128];
    __syncthreads();
    sh[tid] = sxx; __syncthreads();
    if (tid < 128) g_partials[blockIdx.x * 512 + 1 * 128 + c] = sh[tid] + sh[tid + 128];
    __syncthreads();
    sh[tid] = sl;  __syncthreads();
    if (tid < 128) g_partials[blockIdx.x * 512 + 2 * 128 + c] = sh[tid] + sh[tid + 128];
    __syncthreads();
    sh[tid] = sll; __syncthreads();
    if (tid < 128) g_partials[blockIdx.x * 512 + 3 * 128 + c] = sh[tid] + sh[tid + 128];
}

// ---------------- BN stats pass 2 -------------------------------------------
__global__ void stats_final(const float* __restrict__ gamma, const float* __restrict__ beta) {
    int k = threadIdx.x;
    int base = (k < 128) ? 0 : 2;
    int c = k & 127;
    float s = 0.f, ss = 0.f;
    for (int b = 0; b < STATS_BLOCKS; b++) {
        s  += g_partials[b * 512 + base * 128 + c];
        ss += g_partials[b * 512 + (base + 1) * 128 + c];
    }
    float mean = s / (float)MTOT;
    float var  = ss / (float)MTOT - mean * mean;
    float sc   = rsqrtf(var + EPSV) * gamma[k];
    g_scale[k] = sc;
    g_shift[k] = beta[k] - mean * sc;
}

// ---------------- fold BN into linear weights -------------------------------
__global__ void weff_kernel(const float* __restrict__ w, const float* __restrict__ b) {
    int tid = threadIdx.x;  // 256 = k
    float sc = g_scale[tid];
    for (int j = 0; j < 128; j++)
        g_wT[tid * 128 + j] = w[j * 256 + tid] * sc;
    if (tid < 128) {
        float s = b[tid];
        for (int k = 0; k < 256; k++)
            s += g_shift[k] * w[tid * 256 + k];
        g_beff[tid] = s;
    }
}

// ---------------- small GEMM: [X|LX](8192x256) @ wT(256x128) + epilogue -----
__global__ __launch_bounds__(256) void linear_kernel(int xsel,
                                                     const float* __restrict__ resid,
                                                     float* __restrict__ dst, int mode) {
    __shared__ float As[2][16][68];
    __shared__ float Bs[2][16][128];

    const float* __restrict__ X = xsel ? g_bufX2 : g_bufX;

    const int tid  = threadIdx.x;
    const int m0   = blockIdx.x * 64;
    const int rowA = tid >> 2;
    const int colA = (tid & 3) << 2;
    const int rowB = tid >> 4;
    const int colB = (tid & 15) << 3;
    const int ty   = tid >> 4;
    const int tx   = tid & 15;

    float acc[4][8];
#pragma unroll
    for (int i = 0; i < 4; i++)
#pragma unroll
        for (int j = 0; j < 8; j++) acc[i][j] = 0.f;

    const int T = FEAT / 16;

    {
        const float* s = X + (size_t)(m0 + rowA) * DIM + colA;
        float4 a = *(const float4*)s;
        As[0][colA + 0][rowA] = a.x;
        As[0][colA + 1][rowA] = a.y;
        As[0][colA + 2][rowA] = a.z;
        As[0][colA + 3][rowA] = a.w;
        const float* bp = g_wT + rowB * DIM + colB;
        *(float4*)&Bs[0][rowB][colB]     = *(const float4*)bp;
        *(float4*)&Bs[0][rowB][colB + 4] = *(const float4*)(bp + 4);
    }

    int buf = 0;
    for (int t = 0; t < T; ++t) {
        __syncthreads();
        float4 na, nb0, nb1;
        const bool more = (t + 1) < T;
        if (more) {
            int kk = (t + 1) * 16 + colA;
            if (kk < 128) {
                na = *(const float4*)(X + (size_t)(m0 + rowA) * DIM + kk);
            } else {
                size_t idx = (size_t)(m0 + rowA) * DIM + (kk - 128);
                float4 a0 = *(const float4*)(g_Lx0 + idx);
                float4 a1 = *(const float4*)(g_Lx1 + idx);
                na = make_float4(a0.x + a1.x, a0.y + a1.y, a0.z + a1.z, a0.w + a1.w);
            }
            const float* bp = g_wT + (size_t)((t + 1) * 16 + rowB) * DIM + colB;
            nb0 = *(const float4*)bp;
            nb1 = *(const float4*)(bp + 4);
        }
#pragma unroll
        for (int k = 0; k < 16; k++) {
            float4 av  = *(const float4*)&As[buf][k][ty << 2];
            float4 bvA = *(const float4*)&Bs[buf][k][tx << 3];
            float4 bvB = *(const float4*)&Bs[buf][k][(tx << 3) + 4];
            float arv[4] = {av.x, av.y, av.z, av.w};
            float brv[8] = {bvA.x, bvA.y, bvA.z, bvA.w, bvB.x, bvB.y, bvB.z, bvB.w};
#pragma unroll
            for (int i = 0; i < 4; i++)
#pragma unroll
                for (int j = 0; j < 8; j++) acc[i][j] = fmaf(arv[i], brv[j], acc[i][j]);
        }
        if (more) {
            int nb = buf ^ 1;
            As[nb][colA + 0][rowA] = na.x;
            As[nb][colA + 1][rowA] = na.y;
            As[nb][colA + 2][rowA] = na.z;
            As[nb][colA + 3][rowA] = na.w;
            *(float4*)&Bs[nb][rowB][colB]     = nb0;
            *(float4*)&Bs[nb][rowB][colB + 4] = nb1;
            buf = nb;
        }
    }

    float* o = (mode == 0) ? g_bufX2 : dst;
    const int row = m0 + (ty << 2);
    const int col = tx << 3;
#pragma unroll
    for (int i = 0; i < 4; i++) {
        float yv[8];
#pragma unroll
        for (int j = 0; j < 8; j++) {
            float y = acc[i][j] + g_beff[col + j];
            if (mode == 0) {
                yv[j] = y > 0.f ? y : expm1f(y);
            } else {
                yv[j] = y + resid[(size_t)(row + i) * DIM + col + j];
            }
        }
        *(float4*)(o + (size_t)(row + i) * DIM + col)     = make_float4(yv[0], yv[1], yv[2], yv[3]);
        *(float4*)(o + (size_t)(row + i) * DIM + col + 4) = make_float4(yv[4], yv[5], yv[6], yv[7]);
    }
}

// ---------------- launch ----------------------------------------------------
extern "C" void kernel_launch(void* const* d_in, const int* in_sizes, int n_in,
                              void* d_out, int out_size) {
    const float* L      = (const float*)d_in[0];
    const float* inputs = (const float*)d_in[2];
    const float* bn0_g  = (const float*)d_in[3];
    const float* bn0_b  = (const float*)d_in[4];
    const float* fc0_w  = (const float*)d_in[5];
    const float* fc0_b  = (const float*)d_in[6];
    const float* bn1_g  = (const float*)d_in[7];
    const float* bn1_b  = (const float*)d_in[8];
    const float* fc1_w  = (const float*)d_in[9];
    const float* fc1_b  = (const float*)d_in[10];
    float* out = (float*)d_out;

    static int smem_set = 0;
    if (!smem_set) {
        cudaFuncSetAttribute(sgemm_mma, cudaFuncAttributeMaxDynamicSharedMemorySize, SGEMM_SMEM);
        smem_set = 1;
    }

    // x = elu(inputs)
    elu_kernel<<<(MTOT * DIM / 4) / 256, 256>>>(inputs);

    // ---- block 0 ----
    pack_kernel<<<128, 256>>>(0);
    sgemm_mma<<<128, 256, SGEMM_SMEM>>>(L);
    stats_partial<<<STATS_BLOCKS, 256>>>(0);
    stats_final<<<1, 256>>>(bn0_g, bn0_b);
    weff_kernel<<<1, 256>>>(fc0_w, fc0_b);
    linear_kernel<<<MTOT / 64, 256>>>(0, nullptr, nullptr, 0);

    // ---- block 1 ----
    pack_kernel<<<128, 256>>>(1);
    sgemm_mma<<<128, 256, SGEMM_SMEM>>>(L);
    stats_partial<<<STATS_BLOCKS, 256>>>(1);
    stats_final<<<1, 256>>>(bn1_g, bn1_b);
    weff_kernel<<<1, 256>>>(fc1_w, fc1_b);
    linear_kernel<<<MTOT / 64, 256>>>(1, inputs, out, 1);
}

// round 5
// speedup vs baseline: 3.4187x; 1.1533x over previous
#include <cuda_runtime.h>
#include <cuda_bf16.h>
#include <math.h>
#include <stdint.h>

#define MTOT 8192
#define KDIM 8192
#define DIM 128
#define FEAT 256
#define EPSV 1e-5f
#define STATS_BLOCKS 256
#define NKSL 4

// ---------------- scratch (device globals; no allocs allowed) ----------------
__device__ float g_bufX [MTOT * DIM];        // activations entering a block (fp32)
__device__ float g_bufX2[MTOT * DIM];        // activations entering block 2 (fp32)
__device__ float g_LxP [NKSL * MTOT * DIM];  // partial L@x per K slice
// B^T operand, bf16 hi/lo: row-major [feat 128][node 8192]
__device__ __nv_bfloat16 g_Bh[DIM * MTOT];
__device__ __nv_bfloat16 g_Bl[DIM * MTOT];
__device__ float g_partials[STATS_BLOCKS * 4 * DIM];
__device__ float g_scale[FEAT];
__device__ float g_shift[FEAT];
__device__ float g_wT[FEAT * DIM];
__device__ float g_beff[DIM];

// ---------------- helpers ----------------
__device__ __forceinline__ uint32_t smem_u32(const void* p) {
    uint32_t a;
    asm("{ .reg .u64 t; cvta.to.shared.u64 t, %1; cvt.u32.u64 %0, t; }" : "=r"(a) : "l"(p));
    return a;
}
__device__ __forceinline__ void ldmx4(uint32_t* r, uint32_t addr) {
    asm volatile("ldmatrix.sync.aligned.m8n8.x4.shared.b16 {%0,%1,%2,%3}, [%4];"
                 : "=r"(r[0]), "=r"(r[1]), "=r"(r[2]), "=r"(r[3]) : "r"(addr));
}
__device__ __forceinline__ void mma_bf16(float* d, const uint32_t* a, uint32_t b0, uint32_t b1) {
    asm volatile(
        "mma.sync.aligned.m16n8k16.row.col.f32.bf16.bf16.f32 "
        "{%0,%1,%2,%3}, {%4,%5,%6,%7}, {%8,%9}, {%0,%1,%2,%3};"
        : "+f"(d[0]), "+f"(d[1]), "+f"(d[2]), "+f"(d[3])
        : "r"(a[0]), "r"(a[1]), "r"(a[2]), "r"(a[3]), "r"(b0), "r"(b1));
}
__device__ __forceinline__ void cpasync16(uint32_t dst, const void* src) {
    asm volatile("cp.async.cg.shared.global [%0], [%1], 16;" :: "r"(dst), "l"(src));
}
__device__ __forceinline__ void cp_commit() { asm volatile("cp.async.commit_group;"); }
__device__ __forceinline__ void cp_wait0()  { asm volatile("cp.async.wait_group 0;" ::: "memory"); }

__device__ __forceinline__ float eluf(float v) { return v > 0.f ? v : expm1f(v); }

// ---------------- pack: src (node-major fp32) -> B^T (feat-major bf16 hi/lo) --
// mode 0: src = ext_src (network inputs), apply ELU, mirror post-ELU to g_bufX.
// mode 1: src = g_bufX2 (device-resolved!), no ELU.
__global__ __launch_bounds__(256) void pack_kernel(const float* __restrict__ ext_src,
                                                   int mode) {
    __shared__ float tile[128][65];   // [feat][node_local]
    const int tid = threadIdx.x;
    const int node0 = blockIdx.x * 64;
    const float* __restrict__ src = (mode == 0) ? ext_src : g_bufX2;
    const int do_elu = (mode == 0);

    const float4* sv = (const float4*)src + (size_t)node0 * 32;
    float4* xv = (float4*)g_bufX + (size_t)node0 * 32;
#pragma unroll
    for (int i = 0; i < 8; i++) {
        int idx = tid + 256 * i;          // float4 index within 64x128 tile
        int node = idx >> 5;              // 0..63
        int fq = idx & 31;                // float4 within row
        float4 v = sv[idx];
        if (do_elu) {
            v.x = eluf(v.x); v.y = eluf(v.y); v.z = eluf(v.z); v.w = eluf(v.w);
            xv[idx] = v;
        }
        tile[fq * 4 + 0][node] = v.x;
        tile[fq * 4 + 1][node] = v.y;
        tile[fq * 4 + 2][node] = v.z;
        tile[fq * 4 + 3][node] = v.w;
    }
    __syncthreads();

    const int feat = tid >> 1;
    const int h = tid & 1;                // 32-node half
    const float* r = &tile[feat][h * 32];
    uint32_t hi[16], lo[16];
#pragma unroll
    for (int j = 0; j < 16; j++) {
        float a = r[2 * j], b = r[2 * j + 1];
        __nv_bfloat162 hb = __floats2bfloat162_rn(a, b);
        float ha = __low2float(hb), hbv = __high2float(hb);
        __nv_bfloat162 lb = __floats2bfloat162_rn(a - ha, b - hbv);
        hi[j] = *(uint32_t*)&hb;
        lo[j] = *(uint32_t*)&lb;
    }
    uint4* oh = (uint4*)(g_Bh + (size_t)feat * MTOT + node0 + h * 32);
    uint4* ol = (uint4*)(g_Bl + (size_t)feat * MTOT + node0 + h * 32);
#pragma unroll
    for (int blk = 0; blk < 4; blk++) {
        oh[blk] = make_uint4(hi[4 * blk], hi[4 * blk + 1], hi[4 * blk + 2], hi[4 * blk + 3]);
        ol[blk] = make_uint4(lo[4 * blk], lo[4 * blk + 1], lo[4 * blk + 2], lo[4 * blk + 3]);
    }
}

// ---------------- split-bf16 HMMA GEMM: LxP[ksl] = L[:,slice] @ X[slice] ----
// 256 CTAs = 64 M-tiles x 4 K-slices, 2 CTAs/SM. CTA: M=128,N=128,BK=32,K=2048.
#define ROWB 80
#define OPSZ 10240
#define STGSZ 40960
#define SGEMM_SMEM (2 * STGSZ)

__global__ __launch_bounds__(256, 2) void sgemm_mma(const float* __restrict__ L) {
    extern __shared__ char smem[];
    const int tid = threadIdx.x;
    const int lane = tid & 31;
    const int w = tid >> 5;
    const int wm = w >> 1;                 // 0..3 : M 32-row band
    const int wn = w & 1;                  // 0..1 : N 64-col band
    const int mtile = blockIdx.x >> 2;
    const int ksl = blockIdx.x & 3;
    const int m0 = mtile * 128;
    const int kc0 = ksl * 2048;

    const uint32_t sb = smem_u32(smem);

    // ldmatrix per-lane offsets (bytes within an operand block)
    const int a_row = wm * 32 + (lane & 7) + ((lane >> 3) & 1) * 8;
    const uint32_t aOff = (uint32_t)a_row * ROWB + ((lane >> 4) & 1) * 16;
    const int b_row = wn * 64 + (lane & 7) + ((lane >> 4) & 1) * 8;
    const uint32_t bOff = (uint32_t)b_row * ROWB + ((lane >> 3) & 1) * 16;

    // global load assignment
    const int grow = tid >> 1;             // 0..127
    const int gh = tid & 1;                // k half (16 elems)
    const float* Ap = L + (size_t)(m0 + grow) * KDIM + kc0 + gh * 16;
    const __nv_bfloat16* Bhp = g_Bh + (size_t)grow * MTOT + kc0 + gh * 16;
    const __nv_bfloat16* Blp = g_Bl + (size_t)grow * MTOT + kc0 + gh * 16;
    const uint32_t aStOff = (uint32_t)grow * ROWB + gh * 32;  // bytes

    float acc[2][8][4];
#pragma unroll
    for (int i = 0; i < 2; i++)
#pragma unroll
        for (int j = 0; j < 8; j++)
#pragma unroll
            for (int q = 0; q < 4; q++) acc[i][j][q] = 0.f;

    float4 ar[4];

    // prologue: B tile 0 via cp.async into stage 0; A tile 0 via regs
    cpasync16(sb + 2 * OPSZ + aStOff,      Bhp);
    cpasync16(sb + 2 * OPSZ + aStOff + 16, Bhp + 8);
    cpasync16(sb + 3 * OPSZ + aStOff,      Blp);
    cpasync16(sb + 3 * OPSZ + aStOff + 16, Blp + 8);
    cp_commit();
#pragma unroll
    for (int i = 0; i < 4; i++) ar[i] = *(const float4*)(Ap + 4 * i);
    {
        char* sAh = smem + aStOff;
        char* sAl = smem + OPSZ + aStOff;
#pragma unroll
        for (int i = 0; i < 4; i++) {
            float4 v = ar[i];
            __nv_bfloat162 h01 = __floats2bfloat162_rn(v.x, v.y);
            __nv_bfloat162 h23 = __floats2bfloat162_rn(v.z, v.w);
            __nv_bfloat162 l01 = __floats2bfloat162_rn(v.x - __low2float(h01), v.y - __high2float(h01));
            __nv_bfloat162 l23 = __floats2bfloat162_rn(v.z - __low2float(h23), v.w - __high2float(h23));
            *(uint2*)(sAh + 8 * i) = make_uint2(*(uint32_t*)&h01, *(uint32_t*)&h23);
            *(uint2*)(sAl + 8 * i) = make_uint2(*(uint32_t*)&l01, *(uint32_t*)&l23);
        }
    }

    const int T = 2048 / 32;  // 64

    for (int t = 0; t < T; t++) {
        cp_wait0();
        __syncthreads();
        const int s = t & 1;
        const uint32_t sA = sb + s * STGSZ;
        const uint32_t nsBase = sb + (s ^ 1) * STGSZ;
        const bool more = (t + 1) < T;
        if (more) {
            const int off = (t + 1) * 32;
            cpasync16(nsBase + 2 * OPSZ + aStOff,      Bhp + off);
            cpasync16(nsBase + 2 * OPSZ + aStOff + 16, Bhp + off + 8);
            cpasync16(nsBase + 3 * OPSZ + aStOff,      Blp + off);
            cpasync16(nsBase + 3 * OPSZ + aStOff + 16, Blp + off + 8);
            cp_commit();
#pragma unroll
            for (int i = 0; i < 4; i++) ar[i] = *(const float4*)(Ap + off + 4 * i);
        }

        // ---- compute from current stage ----
#pragma unroll
        for (int ks = 0; ks < 2; ks++) {
            const uint32_t kb = ks * 32;  // 16 halfs
            uint32_t Ah[2][4], Al[2][4];
#pragma unroll
            for (int mf = 0; mf < 2; mf++) {
                ldmx4(Ah[mf], sA + aOff + mf * (16 * ROWB) + kb);
                ldmx4(Al[mf], sA + OPSZ + aOff + mf * (16 * ROWB) + kb);
            }
#pragma unroll
            for (int qh = 0; qh < 2; qh++) {
                uint32_t Bh2[2][4], Bl2[2][4];
#pragma unroll
                for (int qq = 0; qq < 2; qq++) {
                    const int q = qh * 2 + qq;
                    ldmx4(Bh2[qq], sA + 2 * OPSZ + bOff + q * (16 * ROWB) + kb);
                    ldmx4(Bl2[qq], sA + 3 * OPSZ + bOff + q * (16 * ROWB) + kb);
                }
#pragma unroll
                for (int mf = 0; mf < 2; mf++)
#pragma unroll
                    for (int qq = 0; qq < 2; qq++)
#pragma unroll
                        for (int j = 0; j < 2; j++) {
                            const int nf = qh * 4 + qq * 2 + j;
                            const int rr = j * 2;
                            mma_bf16(acc[mf][nf], Ah[mf], Bh2[qq][rr], Bh2[qq][rr + 1]);
                            mma_bf16(acc[mf][nf], Ah[mf], Bl2[qq][rr], Bl2[qq][rr + 1]);
                            mma_bf16(acc[mf][nf], Al[mf], Bh2[qq][rr], Bh2[qq][rr + 1]);
                        }
            }
        }

        // ---- convert/store next A tile into other stage ----
        if (more) {
            char* other = smem + (s ^ 1) * STGSZ;
            char* sAh = other + aStOff;
            char* sAl = other + OPSZ + aStOff;
#pragma unroll
            for (int i = 0; i < 4; i++) {
                float4 v = ar[i];
                __nv_bfloat162 h01 = __floats2bfloat162_rn(v.x, v.y);
                __nv_bfloat162 h23 = __floats2bfloat162_rn(v.z, v.w);
                __nv_bfloat162 l01 = __floats2bfloat162_rn(v.x - __low2float(h01), v.y - __high2float(h01));
                __nv_bfloat162 l23 = __floats2bfloat162_rn(v.z - __low2float(h23), v.w - __high2float(h23));
                *(uint2*)(sAh + 8 * i) = make_uint2(*(uint32_t*)&h01, *(uint32_t*)&h23);
                *(uint2*)(sAl + 8 * i) = make_uint2(*(uint32_t*)&l01, *(uint32_t*)&l23);
            }
        }
    }

    // ---- epilogue: write fp32 partials ----
    float* outb = g_LxP + (size_t)ksl * (MTOT * DIM);
    const int g = lane >> 2, t4 = lane & 3;
#pragma unroll
    for (int mf = 0; mf < 2; mf++) {
        const int row0 = m0 + wm * 32 + mf * 16 + g;
#pragma unroll
        for (int nf = 0; nf < 8; nf++) {
            const int col = wn * 64 + nf * 8 + t4 * 2;
            *(float2*)(outb + (size_t)row0 * DIM + col) =
                make_float2(acc[mf][nf][0], acc[mf][nf][1]);
            *(float2*)(outb + (size_t)(row0 + 8) * DIM + col) =
                make_float2(acc[mf][nf][2], acc[mf][nf][3]);
        }
    }
}

// ---------------- BN stats pass 1 -------------------------------------------
__global__ __launch_bounds__(256) void stats_partial(int xsel) {
    const float* __restrict__ X = xsel ? g_bufX2 : g_bufX;
    const int tid = threadIdx.x;
    const int c = tid & 127;
    const int half = tid >> 7;
    const int rpb = MTOT / STATS_BLOCKS;   // 32
    const int r0 = blockIdx.x * rpb;

    float sx = 0.f, sxx = 0.f, sl = 0.f, sll = 0.f;
    for (int r = r0 + half; r < r0 + rpb; r += 2) {
        float v = X[r * DIM + c];
        sx += v; sxx += v * v;
        size_t idx = (size_t)r * DIM + c;
        float w = g_LxP[idx] + g_LxP[idx + (size_t)MTOT * DIM]
                + g_LxP[idx + 2 * (size_t)MTOT * DIM] + g_LxP[idx + 3 * (size_t)MTOT * DIM];
        sl += w; sll += w * w;
    }
    __shared__ float sh[256];
    sh[tid] = sx;  __syncthreads();
    if (tid < 128) g_partials[blockIdx.x * 512 + 0 * 128 + c] = sh[tid] + sh[tid + 128];
    __syncthreads();
    sh[tid] = sxx; __syncthreads();
    if (tid < 128) g_partials[blockIdx.x * 512 + 1 * 128 + c] = sh[tid] + sh[tid + 128];
    __syncthreads();
    sh[tid] = sl;  __syncthreads();
    if (tid < 128) g_partials[blockIdx.x * 512 + 2 * 128 + c] = sh[tid] + sh[tid + 128];
    __syncthreads();
    sh[tid] = sll; __syncthreads();
    if (tid < 128) g_partials[blockIdx.x * 512 + 3 * 128 + c] = sh[tid] + sh[tid + 128];
}

// ---------------- BN stats pass 2 -------------------------------------------
__global__ void stats_final(const float* __restrict__ gamma, const float* __restrict__ beta) {
    int k = threadIdx.x;
    int base = (k < 128) ? 0 : 2;
    int c = k & 127;
    float s = 0.f, ss = 0.f;
    for (int b = 0; b < STATS_BLOCKS; b++) {
        s  += g_partials[b * 512 + base * 128 + c];
        ss += g_partials[b * 512 + (base + 1) * 128 + c];
    }
    float mean = s / (float)MTOT;
    float var  = ss / (float)MTOT - mean * mean;
    float sc   = rsqrtf(var + EPSV) * gamma[k];
    g_scale[k] = sc;
    g_shift[k] = beta[k] - mean * sc;
}

// ---------------- fold BN into linear weights -------------------------------
__global__ void weff_kernel(const float* __restrict__ w, const float* __restrict__ b) {
    int tid = threadIdx.x;  // 256 = k
    float sc = g_scale[tid];
    for (int j = 0; j < 128; j++)
        g_wT[tid * 128 + j] = w[j * 256 + tid] * sc;
    if (tid < 128) {
        float s = b[tid];
        for (int k = 0; k < 256; k++)
            s += g_shift[k] * w[tid * 256 + k];
        g_beff[tid] = s;
    }
}

// ---------------- small GEMM: [X|LX](8192x256) @ wT(256x128) + epilogue -----
__global__ __launch_bounds__(256) void linear_kernel(int xsel,
                                                     const float* __restrict__ resid,
                                                     float* __restrict__ dst, int mode) {
    __shared__ float As[2][16][68];
    __shared__ float Bs[2][16][128];

    const float* __restrict__ X = xsel ? g_bufX2 : g_bufX;

    const int tid  = threadIdx.x;
    const int m0   = blockIdx.x * 64;
    const int rowA = tid >> 2;
    const int colA = (tid & 3) << 2;
    const int rowB = tid >> 4;
    const int colB = (tid & 15) << 3;
    const int ty   = tid >> 4;
    const int tx   = tid & 15;

    float acc[4][8];
#pragma unroll
    for (int i = 0; i < 4; i++)
#pragma unroll
        for (int j = 0; j < 8; j++) acc[i][j] = 0.f;

    const int T = FEAT / 16;

    {
        const float* s = X + (size_t)(m0 + rowA) * DIM + colA;
        float4 a = *(const float4*)s;
        As[0][colA + 0][rowA] = a.x;
        As[0][colA + 1][rowA] = a.y;
        As[0][colA + 2][rowA] = a.z;
        As[0][colA + 3][rowA] = a.w;
        const float* bp = g_wT + rowB * DIM + colB;
        *(float4*)&Bs[0][rowB][colB]     = *(const float4*)bp;
        *(float4*)&Bs[0][rowB][colB + 4] = *(const float4*)(bp + 4);
    }

    int buf = 0;
    for (int t = 0; t < T; ++t) {
        __syncthreads();
        float4 na, nb0, nb1;
        const bool more = (t + 1) < T;
        if (more) {
            int kk = (t + 1) * 16 + colA;
            if (kk < 128) {
                na = *(const float4*)(X + (size_t)(m0 + rowA) * DIM + kk);
            } else {
                size_t idx = (size_t)(m0 + rowA) * DIM + (kk - 128);
                float4 a0 = *(const float4*)(g_LxP + idx);
                float4 a1 = *(const float4*)(g_LxP + idx + (size_t)MTOT * DIM);
                float4 a2 = *(const float4*)(g_LxP + idx + 2 * (size_t)MTOT * DIM);
                float4 a3 = *(const float4*)(g_LxP + idx + 3 * (size_t)MTOT * DIM);
                na = make_float4(a0.x + a1.x + a2.x + a3.x, a0.y + a1.y + a2.y + a3.y,
                                 a0.z + a1.z + a2.z + a3.z, a0.w + a1.w + a2.w + a3.w);
            }
            const float* bp = g_wT + (size_t)((t + 1) * 16 + rowB) * DIM + colB;
            nb0 = *(const float4*)bp;
            nb1 = *(const float4*)(bp + 4);
        }
#pragma unroll
        for (int k = 0; k < 16; k++) {
            float4 av  = *(const float4*)&As[buf][k][ty << 2];
            float4 bvA = *(const float4*)&Bs[buf][k][tx << 3];
            float4 bvB = *(const float4*)&Bs[buf][k][(tx << 3) + 4];
            float arv[4] = {av.x, av.y, av.z, av.w};
            float brv[8] = {bvA.x, bvA.y, bvA.z, bvA.w, bvB.x, bvB.y, bvB.z, bvB.w};
#pragma unroll
            for (int i = 0; i < 4; i++)
#pragma unroll
                for (int j = 0; j < 8; j++) acc[i][j] = fmaf(arv[i], brv[j], acc[i][j]);
        }
        if (more) {
            int nb = buf ^ 1;
            As[nb][colA + 0][rowA] = na.x;
            As[nb][colA + 1][rowA] = na.y;
            As[nb][colA + 2][rowA] = na.z;
            As[nb][colA + 3][rowA] = na.w;
            *(float4*)&Bs[nb][rowB][colB]     = nb0;
            *(float4*)&Bs[nb][rowB][colB + 4] = nb1;
            buf = nb;
        }
    }

    float* o = (mode == 0) ? g_bufX2 : dst;
    const int row = m0 + (ty << 2);
    const int col = tx << 3;
#pragma unroll
    for (int i = 0; i < 4; i++) {
        float yv[8];
#pragma unroll
        for (int j = 0; j < 8; j++) {
            float y = acc[i][j] + g_beff[col + j];
            if (mode == 0) {
                yv[j] = y > 0.f ? y : expm1f(y);
            } else {
                yv[j] = y + resid[(size_t)(row + i) * DIM + col + j];
            }
        }
        *(float4*)(o + (size_t)(row + i) * DIM + col)     = make_float4(yv[0], yv[1], yv[2], yv[3]);
        *(float4*)(o + (size_t)(row + i) * DIM + col + 4) = make_float4(yv[4], yv[5], yv[6], yv[7]);
    }
}

// ---------------- launch ----------------------------------------------------
extern "C" void kernel_launch(void* const* d_in, const int* in_sizes, int n_in,
                              void* d_out, int out_size) {
    const float* L      = (const float*)d_in[0];
    const float* inputs = (const float*)d_in[2];
    const float* bn0_g  = (const float*)d_in[3];
    const float* bn0_b  = (const float*)d_in[4];
    const float* fc0_w  = (const float*)d_in[5];
    const float* fc0_b  = (const float*)d_in[6];
    const float* bn1_g  = (const float*)d_in[7];
    const float* bn1_b  = (const float*)d_in[8];
    const float* fc1_w  = (const float*)d_in[9];
    const float* fc1_b  = (const float*)d_in[10];
    float* out = (float*)d_out;

    cudaFuncSetAttribute(sgemm_mma, cudaFuncAttributeMaxDynamicSharedMemorySize, SGEMM_SMEM);

    // ---- block 0 ----  (pack fuses ELU and mirrors post-ELU x to g_bufX)
    pack_kernel<<<128, 256>>>(inputs, 0);
    sgemm_mma<<<256, 256, SGEMM_SMEM>>>(L);
    stats_partial<<<STATS_BLOCKS, 256>>>(0);
    stats_final<<<1, 256>>>(bn0_g, bn0_b);
    weff_kernel<<<1, 256>>>(fc0_w, fc0_b);
    linear_kernel<<<MTOT / 64, 256>>>(0, nullptr, nullptr, 0);

    // ---- block 1 ----  (source resolved inside the kernel: g_bufX2)
    pack_kernel<<<128, 256>>>(nullptr, 1);
    sgemm_mma<<<256, 256, SGEMM_SMEM>>>(L);
    stats_partial<<<STATS_BLOCKS, 256>>>(1);
    stats_final<<<1, 256>>>(bn1_g, bn1_b);
    weff_kernel<<<1, 256>>>(fc1_w, fc1_b);
    linear_kernel<<<MTOT / 64, 256>>>(1, inputs, out, 1);
}

// round 6
// speedup vs baseline: 4.0529x; 1.1855x over previous
#include <cuda_runtime.h>
#include <cuda_bf16.h>
#include <math.h>
#include <stdint.h>

#define MTOT 8192
#define KDIM 8192
#define DIM 128
#define FEAT 256
#define EPSV 1e-5f
#define STATS_BLOCKS 256
#define NKSL 4

// ---------------- scratch (device globals; no allocs allowed) ----------------
__device__ float g_bufX [MTOT * DIM];        // activations entering a block (fp32)
__device__ float g_bufX2[MTOT * DIM];        // activations entering block 2 (fp32)
__device__ float g_LxP [NKSL * MTOT * DIM];  // partial L@x per K slice (slice 0 becomes sum)
// B^T operand, bf16 hi/lo: row-major [feat 128][node 8192]
__device__ __nv_bfloat16 g_Bh[DIM * MTOT];
__device__ __nv_bfloat16 g_Bl[DIM * MTOT];
__device__ float g_partials[STATS_BLOCKS * 4 * DIM];
__device__ float g_scale[FEAT];
__device__ float g_shift[FEAT];
__device__ float g_wT[FEAT * DIM];
__device__ float g_beff[DIM];

// ---------------- helpers ----------------
__device__ __forceinline__ uint32_t smem_u32(const void* p) {
    uint32_t a;
    asm("{ .reg .u64 t; cvta.to.shared.u64 t, %1; cvt.u32.u64 %0, t; }" : "=r"(a) : "l"(p));
    return a;
}
__device__ __forceinline__ void ldmx4(uint32_t* r, uint32_t addr) {
    asm volatile("ldmatrix.sync.aligned.m8n8.x4.shared.b16 {%0,%1,%2,%3}, [%4];"
                 : "=r"(r[0]), "=r"(r[1]), "=r"(r[2]), "=r"(r[3]) : "r"(addr));
}
__device__ __forceinline__ void mma_bf16(float* d, const uint32_t* a, uint32_t b0, uint32_t b1) {
    asm volatile(
        "mma.sync.aligned.m16n8k16.row.col.f32.bf16.bf16.f32 "
        "{%0,%1,%2,%3}, {%4,%5,%6,%7}, {%8,%9}, {%0,%1,%2,%3};"
        : "+f"(d[0]), "+f"(d[1]), "+f"(d[2]), "+f"(d[3])
        : "r"(a[0]), "r"(a[1]), "r"(a[2]), "r"(a[3]), "r"(b0), "r"(b1));
}
__device__ __forceinline__ void cpasync16(uint32_t dst, const void* src) {
    asm volatile("cp.async.cg.shared.global [%0], [%1], 16;" :: "r"(dst), "l"(src));
}
__device__ __forceinline__ void cp_commit() { asm volatile("cp.async.commit_group;"); }
__device__ __forceinline__ void cp_wait0()  { asm volatile("cp.async.wait_group 0;" ::: "memory"); }

__device__ __forceinline__ float eluf(float v) { return v > 0.f ? v : expm1f(v); }

__device__ __forceinline__ float warp_sum(float v) {
#pragma unroll
    for (int o = 16; o > 0; o >>= 1) v += __shfl_xor_sync(0xFFFFFFFFu, v, o);
    return v;
}

// ---------------- pack: src (node-major fp32) -> B^T (feat-major bf16 hi/lo) --
// mode 0: src = ext_src (network inputs), apply ELU, mirror post-ELU to g_bufX.
// mode 1: src = g_bufX2 (device-resolved), no ELU.
__global__ __launch_bounds__(256) void pack_kernel(const float* __restrict__ ext_src,
                                                   int mode) {
    __shared__ float tile[128][65];   // [feat][node_local]
    const int tid = threadIdx.x;
    const int node0 = blockIdx.x * 64;
    const float* __restrict__ src = (mode == 0) ? ext_src : g_bufX2;
    const int do_elu = (mode == 0);

    const float4* sv = (const float4*)src + (size_t)node0 * 32;
    float4* xv = (float4*)g_bufX + (size_t)node0 * 32;
#pragma unroll
    for (int i = 0; i < 8; i++) {
        int idx = tid + 256 * i;          // float4 index within 64x128 tile
        int node = idx >> 5;              // 0..63
        int fq = idx & 31;                // float4 within row
        float4 v = sv[idx];
        if (do_elu) {
            v.x = eluf(v.x); v.y = eluf(v.y); v.z = eluf(v.z); v.w = eluf(v.w);
            xv[idx] = v;
        }
        tile[fq * 4 + 0][node] = v.x;
        tile[fq * 4 + 1][node] = v.y;
        tile[fq * 4 + 2][node] = v.z;
        tile[fq * 4 + 3][node] = v.w;
    }
    __syncthreads();

    const int feat = tid >> 1;
    const int h = tid & 1;                // 32-node half
    const float* r = &tile[feat][h * 32];
    uint32_t hi[16], lo[16];
#pragma unroll
    for (int j = 0; j < 16; j++) {
        float a = r[2 * j], b = r[2 * j + 1];
        __nv_bfloat162 hb = __floats2bfloat162_rn(a, b);
        float ha = __low2float(hb), hbv = __high2float(hb);
        __nv_bfloat162 lb = __floats2bfloat162_rn(a - ha, b - hbv);
        hi[j] = *(uint32_t*)&hb;
        lo[j] = *(uint32_t*)&lb;
    }
    uint4* oh = (uint4*)(g_Bh + (size_t)feat * MTOT + node0 + h * 32);
    uint4* ol = (uint4*)(g_Bl + (size_t)feat * MTOT + node0 + h * 32);
#pragma unroll
    for (int blk = 0; blk < 4; blk++) {
        oh[blk] = make_uint4(hi[4 * blk], hi[4 * blk + 1], hi[4 * blk + 2], hi[4 * blk + 3]);
        ol[blk] = make_uint4(lo[4 * blk], lo[4 * blk + 1], lo[4 * blk + 2], lo[4 * blk + 3]);
    }
}

// ---------------- split-bf16 HMMA GEMM: LxP[ksl] = L[:,slice] @ X[slice] ----
// 256 CTAs = 64 M-tiles x 4 K-slices, 2 CTAs/SM. CTA: M=128,N=128,BK=32,K=2048.
#define ROWB 80
#define OPSZ 10240
#define STGSZ 40960
#define SGEMM_SMEM (2 * STGSZ)

__global__ __launch_bounds__(256, 2) void sgemm_mma(const float* __restrict__ L) {
    extern __shared__ char smem[];
    const int tid = threadIdx.x;
    const int lane = tid & 31;
    const int w = tid >> 5;
    const int wm = w >> 1;                 // 0..3 : M 32-row band
    const int wn = w & 1;                  // 0..1 : N 64-col band
    const int mtile = blockIdx.x >> 2;
    const int ksl = blockIdx.x & 3;
    const int m0 = mtile * 128;
    const int kc0 = ksl * 2048;

    const uint32_t sb = smem_u32(smem);

    const int a_row = wm * 32 + (lane & 7) + ((lane >> 3) & 1) * 8;
    const uint32_t aOff = (uint32_t)a_row * ROWB + ((lane >> 4) & 1) * 16;
    const int b_row = wn * 64 + (lane & 7) + ((lane >> 4) & 1) * 8;
    const uint32_t bOff = (uint32_t)b_row * ROWB + ((lane >> 3) & 1) * 16;

    const int grow = tid >> 1;             // 0..127
    const int gh = tid & 1;                // k half (16 elems)
    const float* Ap = L + (size_t)(m0 + grow) * KDIM + kc0 + gh * 16;
    const __nv_bfloat16* Bhp = g_Bh + (size_t)grow * MTOT + kc0 + gh * 16;
    const __nv_bfloat16* Blp = g_Bl + (size_t)grow * MTOT + kc0 + gh * 16;
    const uint32_t aStOff = (uint32_t)grow * ROWB + gh * 32;  // bytes

    float acc[2][8][4];
#pragma unroll
    for (int i = 0; i < 2; i++)
#pragma unroll
        for (int j = 0; j < 8; j++)
#pragma unroll
            for (int q = 0; q < 4; q++) acc[i][j][q] = 0.f;

    float4 ar[4];

    cpasync16(sb + 2 * OPSZ + aStOff,      Bhp);
    cpasync16(sb + 2 * OPSZ + aStOff + 16, Bhp + 8);
    cpasync16(sb + 3 * OPSZ + aStOff,      Blp);
    cpasync16(sb + 3 * OPSZ + aStOff + 16, Blp + 8);
    cp_commit();
#pragma unroll
    for (int i = 0; i < 4; i++) ar[i] = *(const float4*)(Ap + 4 * i);
    {
        char* sAh = smem + aStOff;
        char* sAl = smem + OPSZ + aStOff;
#pragma unroll
        for (int i = 0; i < 4; i++) {
            float4 v = ar[i];
            __nv_bfloat162 h01 = __floats2bfloat162_rn(v.x, v.y);
            __nv_bfloat162 h23 = __floats2bfloat162_rn(v.z, v.w);
            __nv_bfloat162 l01 = __floats2bfloat162_rn(v.x - __low2float(h01), v.y - __high2float(h01));
            __nv_bfloat162 l23 = __floats2bfloat162_rn(v.z - __low2float(h23), v.w - __high2float(h23));
            *(uint2*)(sAh + 8 * i) = make_uint2(*(uint32_t*)&h01, *(uint32_t*)&h23);
            *(uint2*)(sAl + 8 * i) = make_uint2(*(uint32_t*)&l01, *(uint32_t*)&l23);
        }
    }

    const int T = 2048 / 32;  // 64

    for (int t = 0; t < T; t++) {
        cp_wait0();
        __syncthreads();
        const int s = t & 1;
        const uint32_t sA = sb + s * STGSZ;
        const uint32_t nsBase = sb + (s ^ 1) * STGSZ;
        const bool more = (t + 1) < T;
        if (more) {
            const int off = (t + 1) * 32;
            cpasync16(nsBase + 2 * OPSZ + aStOff,      Bhp + off);
            cpasync16(nsBase + 2 * OPSZ + aStOff + 16, Bhp + off + 8);
            cpasync16(nsBase + 3 * OPSZ + aStOff,      Blp + off);
            cpasync16(nsBase + 3 * OPSZ + aStOff + 16, Blp + off + 8);
            cp_commit();
#pragma unroll
            for (int i = 0; i < 4; i++) ar[i] = *(const float4*)(Ap + off + 4 * i);
        }

#pragma unroll
        for (int ks = 0; ks < 2; ks++) {
            const uint32_t kb = ks * 32;  // 16 halfs
            uint32_t Ah[2][4], Al[2][4];
#pragma unroll
            for (int mf = 0; mf < 2; mf++) {
                ldmx4(Ah[mf], sA + aOff + mf * (16 * ROWB) + kb);
                ldmx4(Al[mf], sA + OPSZ + aOff + mf * (16 * ROWB) + kb);
            }
#pragma unroll
            for (int qh = 0; qh < 2; qh++) {
                uint32_t Bh2[2][4], Bl2[2][4];
#pragma unroll
                for (int qq = 0; qq < 2; qq++) {
                    const int q = qh * 2 + qq;
                    ldmx4(Bh2[qq], sA + 2 * OPSZ + bOff + q * (16 * ROWB) + kb);
                    ldmx4(Bl2[qq], sA + 3 * OPSZ + bOff + q * (16 * ROWB) + kb);
                }
#pragma unroll
                for (int mf = 0; mf < 2; mf++)
#pragma unroll
                    for (int qq = 0; qq < 2; qq++)
#pragma unroll
                        for (int j = 0; j < 2; j++) {
                            const int nf = qh * 4 + qq * 2 + j;
                            const int rr = j * 2;
                            mma_bf16(acc[mf][nf], Ah[mf], Bh2[qq][rr], Bh2[qq][rr + 1]);
                            mma_bf16(acc[mf][nf], Ah[mf], Bl2[qq][rr], Bl2[qq][rr + 1]);
                            mma_bf16(acc[mf][nf], Al[mf], Bh2[qq][rr], Bh2[qq][rr + 1]);
                        }
            }
        }

        if (more) {
            char* other = smem + (s ^ 1) * STGSZ;
            char* sAh = other + aStOff;
            char* sAl = other + OPSZ + aStOff;
#pragma unroll
            for (int i = 0; i < 4; i++) {
                float4 v = ar[i];
                __nv_bfloat162 h01 = __floats2bfloat162_rn(v.x, v.y);
                __nv_bfloat162 h23 = __floats2bfloat162_rn(v.z, v.w);
                __nv_bfloat162 l01 = __floats2bfloat162_rn(v.x - __low2float(h01), v.y - __high2float(h01));
                __nv_bfloat162 l23 = __floats2bfloat162_rn(v.z - __low2float(h23), v.w - __high2float(h23));
                *(uint2*)(sAh + 8 * i) = make_uint2(*(uint32_t*)&h01, *(uint32_t*)&h23);
                *(uint2*)(sAl + 8 * i) = make_uint2(*(uint32_t*)&l01, *(uint32_t*)&l23);
            }
        }
    }

    // ---- epilogue: write fp32 partials ----
    float* outb = g_LxP + (size_t)ksl * (MTOT * DIM);
    const int g = lane >> 2, t4 = lane & 3;
#pragma unroll
    for (int mf = 0; mf < 2; mf++) {
        const int row0 = m0 + wm * 32 + mf * 16 + g;
#pragma unroll
        for (int nf = 0; nf < 8; nf++) {
            const int col = wn * 64 + nf * 8 + t4 * 2;
            *(float2*)(outb + (size_t)row0 * DIM + col) =
                make_float2(acc[mf][nf][0], acc[mf][nf][1]);
            *(float2*)(outb + (size_t)(row0 + 8) * DIM + col) =
                make_float2(acc[mf][nf][2], acc[mf][nf][3]);
        }
    }
}

// ---------------- BN stats pass 1 + K-split sum fold ------------------------
// Also collapses the 4 LxP slices into slice 0 (same-thread read->write; each
// element touched by exactly one thread; slice 0 fully rewritten by sgemm each
// replay, so graph-replay safe).
__global__ __launch_bounds__(256) void stats_partial(int xsel) {
    const float* __restrict__ X = xsel ? g_bufX2 : g_bufX;
    const int tid = threadIdx.x;
    const int c = tid & 127;
    const int half = tid >> 7;
    const int rpb = MTOT / STATS_BLOCKS;   // 32
    const int r0 = blockIdx.x * rpb;

    float sx = 0.f, sxx = 0.f, sl = 0.f, sll = 0.f;
    for (int r = r0 + half; r < r0 + rpb; r += 2) {
        float v = X[r * DIM + c];
        sx += v; sxx += v * v;
        size_t idx = (size_t)r * DIM + c;
        float w = g_LxP[idx] + g_LxP[idx + (size_t)MTOT * DIM]
                + g_LxP[idx + 2 * (size_t)MTOT * DIM] + g_LxP[idx + 3 * (size_t)MTOT * DIM];
        g_LxP[idx] = w;   // fold sum into slice 0
        sl += w; sll += w * w;
    }
    __shared__ float sh[256];
    sh[tid] = sx;  __syncthreads();
    if (tid < 128) g_partials[blockIdx.x * 512 + 0 * 128 + c] = sh[tid] + sh[tid + 128];
    __syncthreads();
    sh[tid] = sxx; __syncthreads();
    if (tid < 128) g_partials[blockIdx.x * 512 + 1 * 128 + c] = sh[tid] + sh[tid + 128];
    __syncthreads();
    sh[tid] = sl;  __syncthreads();
    if (tid < 128) g_partials[blockIdx.x * 512 + 2 * 128 + c] = sh[tid] + sh[tid + 128];
    __syncthreads();
    sh[tid] = sll; __syncthreads();
    if (tid < 128) g_partials[blockIdx.x * 512 + 3 * 128 + c] = sh[tid] + sh[tid + 128];
}

// ---------------- BN stats pass 2: parallel (1 warp / feature) --------------
__global__ __launch_bounds__(256) void stats_final(const float* __restrict__ gamma,
                                                   const float* __restrict__ beta) {
    const int warp = threadIdx.x >> 5;
    const int lane = threadIdx.x & 31;
    const int k = blockIdx.x * 8 + warp;          // 0..255
    const int base = (k < 128) ? 0 : 2;
    const int c = k & 127;
    float s = 0.f, ss = 0.f;
    for (int b = lane; b < STATS_BLOCKS; b += 32) {
        s  += g_partials[b * 512 + base * 128 + c];
        ss += g_partials[b * 512 + (base + 1) * 128 + c];
    }
    s = warp_sum(s);
    ss = warp_sum(ss);
    if (lane == 0) {
        float mean = s / (float)MTOT;
        float var  = ss / (float)MTOT - mean * mean;
        float sc   = rsqrtf(var + EPSV) * gamma[k];
        g_scale[k] = sc;
        g_shift[k] = beta[k] - mean * sc;
    }
}

// ---------------- fold BN into linear weights (parallel) --------------------
// grid 32 x 256. All blocks: wT scatter (4 elems/thread). Blocks 0..15: beff
// via one warp per output.
__global__ __launch_bounds__(256) void weff_kernel(const float* __restrict__ w,
                                                   const float* __restrict__ b) {
    const int e0 = (blockIdx.x * 256 + threadIdx.x) * 4;   // 0..32764
    const int k = e0 >> 7;
    const int j = e0 & 127;
    const float sc = g_scale[k];
    float4 o;
    o.x = w[(j + 0) * 256 + k] * sc;
    o.y = w[(j + 1) * 256 + k] * sc;
    o.z = w[(j + 2) * 256 + k] * sc;
    o.w = w[(j + 3) * 256 + k] * sc;
    *(float4*)(g_wT + k * 128 + j) = o;

    if (blockIdx.x < 16) {
        const int warp = threadIdx.x >> 5;
        const int lane = threadIdx.x & 31;
        const int jo = blockIdx.x * 8 + warp;     // 0..127
        float s = 0.f;
        for (int kk = lane; kk < 256; kk += 32)
            s += g_shift[kk] * w[jo * 256 + kk];
        s = warp_sum(s);
        if (lane == 0) g_beff[jo] = b[jo] + s;
    }
}

// ---------------- small GEMM: [X|LX](8192x256) @ wT(256x128) + epilogue -----
__global__ __launch_bounds__(256) void linear_kernel(int xsel,
                                                     const float* __restrict__ resid,
                                                     float* __restrict__ dst, int mode) {
    __shared__ float As[2][16][68];
    __shared__ float Bs[2][16][128];

    const float* __restrict__ X = xsel ? g_bufX2 : g_bufX;

    const int tid  = threadIdx.x;
    const int m0   = blockIdx.x * 64;
    const int rowA = tid >> 2;
    const int colA = (tid & 3) << 2;
    const int rowB = tid >> 4;
    const int colB = (tid & 15) << 3;
    const int ty   = tid >> 4;
    const int tx   = tid & 15;

    float acc[4][8];
#pragma unroll
    for (int i = 0; i < 4; i++)
#pragma unroll
        for (int j = 0; j < 8; j++) acc[i][j] = 0.f;

    const int T = FEAT / 16;

    {
        const float* s = X + (size_t)(m0 + rowA) * DIM + colA;
        float4 a = *(const float4*)s;
        As[0][colA + 0][rowA] = a.x;
        As[0][colA + 1][rowA] = a.y;
        As[0][colA + 2][rowA] = a.z;
        As[0][colA + 3][rowA] = a.w;
        const float* bp = g_wT + rowB * DIM + colB;
        *(float4*)&Bs[0][rowB][colB]     = *(const float4*)bp;
        *(float4*)&Bs[0][rowB][colB + 4] = *(const float4*)(bp + 4);
    }

    int buf = 0;
    for (int t = 0; t < T; ++t) {
        __syncthreads();
        float4 na, nb0, nb1;
        const bool more = (t + 1) < T;
        if (more) {
            int kk = (t + 1) * 16 + colA;
            if (kk < 128) {
                na = *(const float4*)(X + (size_t)(m0 + rowA) * DIM + kk);
            } else {
                na = *(const float4*)(g_LxP + (size_t)(m0 + rowA) * DIM + (kk - 128));
            }
            const float* bp = g_wT + (size_t)((t + 1) * 16 + rowB) * DIM + colB;
            nb0 = *(const float4*)bp;
            nb1 = *(const float4*)(bp + 4);
        }
#pragma unroll
        for (int k = 0; k < 16; k++) {
            float4 av  = *(const float4*)&As[buf][k][ty << 2];
            float4 bvA = *(const float4*)&Bs[buf][k][tx << 3];
            float4 bvB = *(const float4*)&Bs[buf][k][(tx << 3) + 4];
            float arv[4] = {av.x, av.y, av.z, av.w};
            float brv[8] = {bvA.x, bvA.y, bvA.z, bvA.w, bvB.x, bvB.y, bvB.z, bvB.w};
#pragma unroll
            for (int i = 0; i < 4; i++)
#pragma unroll
                for (int j = 0; j < 8; j++) acc[i][j] = fmaf(arv[i], brv[j], acc[i][j]);
        }
        if (more) {
            int nb = buf ^ 1;
            As[nb][colA + 0][rowA] = na.x;
            As[nb][colA + 1][rowA] = na.y;
            As[nb][colA + 2][rowA] = na.z;
            As[nb][colA + 3][rowA] = na.w;
            *(float4*)&Bs[nb][rowB][colB]     = nb0;
            *(float4*)&Bs[nb][rowB][colB + 4] = nb1;
            buf = nb;
        }
    }

    float* o = (mode == 0) ? g_bufX2 : dst;
    const int row = m0 + (ty << 2);
    const int col = tx << 3;
#pragma unroll
    for (int i = 0; i < 4; i++) {
        float yv[8];
#pragma unroll
        for (int j = 0; j < 8; j++) {
            float y = acc[i][j] + g_beff[col + j];
            if (mode == 0) {
                yv[j] = y > 0.f ? y : expm1f(y);
            } else {
                yv[j] = y + resid[(size_t)(row + i) * DIM + col + j];
            }
        }
        *(float4*)(o + (size_t)(row + i) * DIM + col)     = make_float4(yv[0], yv[1], yv[2], yv[3]);
        *(float4*)(o + (size_t)(row + i) * DIM + col + 4) = make_float4(yv[4], yv[5], yv[6], yv[7]);
    }
}

// ---------------- launch ----------------------------------------------------
extern "C" void kernel_launch(void* const* d_in, const int* in_sizes, int n_in,
                              void* d_out, int out_size) {
    const float* L      = (const float*)d_in[0];
    const float* inputs = (const float*)d_in[2];
    const float* bn0_g  = (const float*)d_in[3];
    const float* bn0_b  = (const float*)d_in[4];
    const float* fc0_w  = (const float*)d_in[5];
    const float* fc0_b  = (const float*)d_in[6];
    const float* bn1_g  = (const float*)d_in[7];
    const float* bn1_b  = (const float*)d_in[8];
    const float* fc1_w  = (const float*)d_in[9];
    const float* fc1_b  = (const float*)d_in[10];
    float* out = (float*)d_out;

    cudaFuncSetAttribute(sgemm_mma, cudaFuncAttributeMaxDynamicSharedMemorySize, SGEMM_SMEM);

    // ---- block 0 ----
    pack_kernel<<<128, 256>>>(inputs, 0);
    sgemm_mma<<<256, 256, SGEMM_SMEM>>>(L);
    stats_partial<<<STATS_BLOCKS, 256>>>(0);
    stats_final<<<32, 256>>>(bn0_g, bn0_b);
    weff_kernel<<<32, 256>>>(fc0_w, fc0_b);
    linear_kernel<<<MTOT / 64, 256>>>(0, nullptr, nullptr, 0);

    // ---- block 1 ----
    pack_kernel<<<128, 256>>>(nullptr, 1);
    sgemm_mma<<<256, 256, SGEMM_SMEM>>>(L);
    stats_partial<<<STATS_BLOCKS, 256>>>(1);
    stats_final<<<32, 256>>>(bn1_g, bn1_b);
    weff_kernel<<<32, 256>>>(fc1_w, fc1_b);
    linear_kernel<<<MTOT / 64, 256>>>(1, inputs, out, 1);
}

// round 7
// speedup vs baseline: 4.1903x; 1.0339x over previous
#include <cuda_runtime.h>
#include <cuda_bf16.h>
#include <math.h>
#include <stdint.h>

#define MTOT 8192
#define KDIM 8192
#define DIM 128
#define FEAT 256
#define EPSV 1e-5f
#define STATS_BLOCKS 256
#define NKSL 4

// ---------------- scratch (device globals; no allocs allowed) ----------------
__device__ float g_bufX [MTOT * DIM];        // activations entering a block (fp32)
__device__ float g_bufX2[MTOT * DIM];        // activations entering block 2 (fp32)
__device__ float g_LxP [NKSL * MTOT * DIM];  // partial L@x per K slice (slice 0 -> sum)
// B^T operand, bf16 hi/lo: row-major [feat 128][node 8192]
__device__ __nv_bfloat16 g_Bh[DIM * MTOT];
__device__ __nv_bfloat16 g_Bl[DIM * MTOT];
// partials transposed: [quad 0..3][feat 0..127][block 0..255]
__device__ float g_partials[4 * DIM * STATS_BLOCKS];
__device__ float g_scale[FEAT];
__device__ float g_shift[FEAT];
// BN-folded linear weights, bf16 split, row-major [j 128][k 256]
__device__ __nv_bfloat16 g_wBh[DIM * FEAT];
__device__ __nv_bfloat16 g_wBl[DIM * FEAT];
__device__ float g_beff[DIM];

// ---------------- helpers ----------------
__device__ __forceinline__ uint32_t smem_u32(const void* p) {
    uint32_t a;
    asm("{ .reg .u64 t; cvta.to.shared.u64 t, %1; cvt.u32.u64 %0, t; }" : "=r"(a) : "l"(p));
    return a;
}
__device__ __forceinline__ void ldmx4(uint32_t* r, uint32_t addr) {
    asm volatile("ldmatrix.sync.aligned.m8n8.x4.shared.b16 {%0,%1,%2,%3}, [%4];"
                 : "=r"(r[0]), "=r"(r[1]), "=r"(r[2]), "=r"(r[3]) : "r"(addr));
}
__device__ __forceinline__ void mma_bf16(float* d, const uint32_t* a, uint32_t b0, uint32_t b1) {
    asm volatile(
        "mma.sync.aligned.m16n8k16.row.col.f32.bf16.bf16.f32 "
        "{%0,%1,%2,%3}, {%4,%5,%6,%7}, {%8,%9}, {%0,%1,%2,%3};"
        : "+f"(d[0]), "+f"(d[1]), "+f"(d[2]), "+f"(d[3])
        : "r"(a[0]), "r"(a[1]), "r"(a[2]), "r"(a[3]), "r"(b0), "r"(b1));
}
__device__ __forceinline__ void cpasync16(uint32_t dst, const void* src) {
    asm volatile("cp.async.cg.shared.global [%0], [%1], 16;" :: "r"(dst), "l"(src));
}
__device__ __forceinline__ void cp_commit() { asm volatile("cp.async.commit_group;"); }
__device__ __forceinline__ void cp_wait0()  { asm volatile("cp.async.wait_group 0;" ::: "memory"); }

__device__ __forceinline__ float eluf(float v) { return v > 0.f ? v : expm1f(v); }

__device__ __forceinline__ float warp_sum(float v) {
#pragma unroll
    for (int o = 16; o > 0; o >>= 1) v += __shfl_xor_sync(0xFFFFFFFFu, v, o);
    return v;
}
__device__ __forceinline__ void split_bf16(float v, __nv_bfloat16& h, __nv_bfloat16& l) {
    h = __float2bfloat16(v);
    l = __float2bfloat16(v - __bfloat162float(h));
}

// ---------------- pack: inputs -> ELU -> g_bufX + B^T bf16 hi/lo ------------
__global__ __launch_bounds__(256) void pack_kernel(const float* __restrict__ src) {
    __shared__ float tile[128][65];   // [feat][node_local]
    const int tid = threadIdx.x;
    const int node0 = blockIdx.x * 64;

    const float4* sv = (const float4*)src + (size_t)node0 * 32;
    float4* xv = (float4*)g_bufX + (size_t)node0 * 32;
#pragma unroll
    for (int i = 0; i < 8; i++) {
        int idx = tid + 256 * i;
        int node = idx >> 5;
        int fq = idx & 31;
        float4 v = sv[idx];
        v.x = eluf(v.x); v.y = eluf(v.y); v.z = eluf(v.z); v.w = eluf(v.w);
        xv[idx] = v;
        tile[fq * 4 + 0][node] = v.x;
        tile[fq * 4 + 1][node] = v.y;
        tile[fq * 4 + 2][node] = v.z;
        tile[fq * 4 + 3][node] = v.w;
    }
    __syncthreads();

    const int feat = tid >> 1;
    const int h = tid & 1;
    const float* r = &tile[feat][h * 32];
    uint32_t hi[16], lo[16];
#pragma unroll
    for (int j = 0; j < 16; j++) {
        float a = r[2 * j], b = r[2 * j + 1];
        __nv_bfloat162 hb = __floats2bfloat162_rn(a, b);
        float ha = __low2float(hb), hbv = __high2float(hb);
        __nv_bfloat162 lb = __floats2bfloat162_rn(a - ha, b - hbv);
        hi[j] = *(uint32_t*)&hb;
        lo[j] = *(uint32_t*)&lb;
    }
    uint4* oh = (uint4*)(g_Bh + (size_t)feat * MTOT + node0 + h * 32);
    uint4* ol = (uint4*)(g_Bl + (size_t)feat * MTOT + node0 + h * 32);
#pragma unroll
    for (int blk = 0; blk < 4; blk++) {
        oh[blk] = make_uint4(hi[4 * blk], hi[4 * blk + 1], hi[4 * blk + 2], hi[4 * blk + 3]);
        ol[blk] = make_uint4(lo[4 * blk], lo[4 * blk + 1], lo[4 * blk + 2], lo[4 * blk + 3]);
    }
}

// ---------------- split-bf16 HMMA GEMM: LxP[ksl] = L[:,slice] @ X[slice] ----
#define ROWB 80
#define OPSZ 10240
#define STGSZ 40960
#define SGEMM_SMEM (2 * STGSZ)

__global__ __launch_bounds__(256, 2) void sgemm_mma(const float* __restrict__ L) {
    extern __shared__ char smem[];
    const int tid = threadIdx.x;
    const int lane = tid & 31;
    const int w = tid >> 5;
    const int wm = w >> 1;
    const int wn = w & 1;
    const int mtile = blockIdx.x >> 2;
    const int ksl = blockIdx.x & 3;
    const int m0 = mtile * 128;
    const int kc0 = ksl * 2048;

    const uint32_t sb = smem_u32(smem);

    const int a_row = wm * 32 + (lane & 7) + ((lane >> 3) & 1) * 8;
    const uint32_t aOff = (uint32_t)a_row * ROWB + ((lane >> 4) & 1) * 16;
    const int b_row = wn * 64 + (lane & 7) + ((lane >> 4) & 1) * 8;
    const uint32_t bOff = (uint32_t)b_row * ROWB + ((lane >> 3) & 1) * 16;

    const int grow = tid >> 1;
    const int gh = tid & 1;
    const float* Ap = L + (size_t)(m0 + grow) * KDIM + kc0 + gh * 16;
    const __nv_bfloat16* Bhp = g_Bh + (size_t)grow * MTOT + kc0 + gh * 16;
    const __nv_bfloat16* Blp = g_Bl + (size_t)grow * MTOT + kc0 + gh * 16;
    const uint32_t aStOff = (uint32_t)grow * ROWB + gh * 32;

    float acc[2][8][4];
#pragma unroll
    for (int i = 0; i < 2; i++)
#pragma unroll
        for (int j = 0; j < 8; j++)
#pragma unroll
            for (int q = 0; q < 4; q++) acc[i][j][q] = 0.f;

    float4 ar[4];

    cpasync16(sb + 2 * OPSZ + aStOff,      Bhp);
    cpasync16(sb + 2 * OPSZ + aStOff + 16, Bhp + 8);
    cpasync16(sb + 3 * OPSZ + aStOff,      Blp);
    cpasync16(sb + 3 * OPSZ + aStOff + 16, Blp + 8);
    cp_commit();
#pragma unroll
    for (int i = 0; i < 4; i++) ar[i] = *(const float4*)(Ap + 4 * i);
    {
        char* sAh = smem + aStOff;
        char* sAl = smem + OPSZ + aStOff;
#pragma unroll
        for (int i = 0; i < 4; i++) {
            float4 v = ar[i];
            __nv_bfloat162 h01 = __floats2bfloat162_rn(v.x, v.y);
            __nv_bfloat162 h23 = __floats2bfloat162_rn(v.z, v.w);
            __nv_bfloat162 l01 = __floats2bfloat162_rn(v.x - __low2float(h01), v.y - __high2float(h01));
            __nv_bfloat162 l23 = __floats2bfloat162_rn(v.z - __low2float(h23), v.w - __high2float(h23));
            *(uint2*)(sAh + 8 * i) = make_uint2(*(uint32_t*)&h01, *(uint32_t*)&h23);
            *(uint2*)(sAl + 8 * i) = make_uint2(*(uint32_t*)&l01, *(uint32_t*)&l23);
        }
    }

    const int T = 2048 / 32;  // 64

    for (int t = 0; t < T; t++) {
        cp_wait0();
        __syncthreads();
        const int s = t & 1;
        const uint32_t sA = sb + s * STGSZ;
        const uint32_t nsBase = sb + (s ^ 1) * STGSZ;
        const bool more = (t + 1) < T;
        if (more) {
            const int off = (t + 1) * 32;
            cpasync16(nsBase + 2 * OPSZ + aStOff,      Bhp + off);
            cpasync16(nsBase + 2 * OPSZ + aStOff + 16, Bhp + off + 8);
            cpasync16(nsBase + 3 * OPSZ + aStOff,      Blp + off);
            cpasync16(nsBase + 3 * OPSZ + aStOff + 16, Blp + off + 8);
            cp_commit();
#pragma unroll
            for (int i = 0; i < 4; i++) ar[i] = *(const float4*)(Ap + off + 4 * i);
        }

#pragma unroll
        for (int ks = 0; ks < 2; ks++) {
            const uint32_t kb = ks * 32;
            uint32_t Ah[2][4], Al[2][4];
#pragma unroll
            for (int mf = 0; mf < 2; mf++) {
                ldmx4(Ah[mf], sA + aOff + mf * (16 * ROWB) + kb);
                ldmx4(Al[mf], sA + OPSZ + aOff + mf * (16 * ROWB) + kb);
            }
#pragma unroll
            for (int qh = 0; qh < 2; qh++) {
                uint32_t Bh2[2][4], Bl2[2][4];
#pragma unroll
                for (int qq = 0; qq < 2; qq++) {
                    const int q = qh * 2 + qq;
                    ldmx4(Bh2[qq], sA + 2 * OPSZ + bOff + q * (16 * ROWB) + kb);
                    ldmx4(Bl2[qq], sA + 3 * OPSZ + bOff + q * (16 * ROWB) + kb);
                }
#pragma unroll
                for (int mf = 0; mf < 2; mf++)
#pragma unroll
                    for (int qq = 0; qq < 2; qq++)
#pragma unroll
                        for (int j = 0; j < 2; j++) {
                            const int nf = qh * 4 + qq * 2 + j;
                            const int rr = j * 2;
                            mma_bf16(acc[mf][nf], Ah[mf], Bh2[qq][rr], Bh2[qq][rr + 1]);
                            mma_bf16(acc[mf][nf], Ah[mf], Bl2[qq][rr], Bl2[qq][rr + 1]);
                            mma_bf16(acc[mf][nf], Al[mf], Bh2[qq][rr], Bh2[qq][rr + 1]);
                        }
            }
        }

        if (more) {
            char* other = smem + (s ^ 1) * STGSZ;
            char* sAh = other + aStOff;
            char* sAl = other + OPSZ + aStOff;
#pragma unroll
            for (int i = 0; i < 4; i++) {
                float4 v = ar[i];
                __nv_bfloat162 h01 = __floats2bfloat162_rn(v.x, v.y);
                __nv_bfloat162 h23 = __floats2bfloat162_rn(v.z, v.w);
                __nv_bfloat162 l01 = __floats2bfloat162_rn(v.x - __low2float(h01), v.y - __high2float(h01));
                __nv_bfloat162 l23 = __floats2bfloat162_rn(v.z - __low2float(h23), v.w - __high2float(h23));
                *(uint2*)(sAh + 8 * i) = make_uint2(*(uint32_t*)&h01, *(uint32_t*)&h23);
                *(uint2*)(sAl + 8 * i) = make_uint2(*(uint32_t*)&l01, *(uint32_t*)&l23);
            }
        }
    }

    float* outb = g_LxP + (size_t)ksl * (MTOT * DIM);
    const int g = lane >> 2, t4 = lane & 3;
#pragma unroll
    for (int mf = 0; mf < 2; mf++) {
        const int row0 = m0 + wm * 32 + mf * 16 + g;
#pragma unroll
        for (int nf = 0; nf < 8; nf++) {
            const int col = wn * 64 + nf * 8 + t4 * 2;
            *(float2*)(outb + (size_t)row0 * DIM + col) =
                make_float2(acc[mf][nf][0], acc[mf][nf][1]);
            *(float2*)(outb + (size_t)(row0 + 8) * DIM + col) =
                make_float2(acc[mf][nf][2], acc[mf][nf][3]);
        }
    }
}

// ---------------- BN stats pass 1 + K-split fold (transposed partials) ------
__global__ __launch_bounds__(256) void stats_partial(int xsel) {
    const float* __restrict__ X = xsel ? g_bufX2 : g_bufX;
    const int tid = threadIdx.x;
    const int c = tid & 127;
    const int half = tid >> 7;
    const int rpb = MTOT / STATS_BLOCKS;   // 32
    const int r0 = blockIdx.x * rpb;

    float sx = 0.f, sxx = 0.f, sl = 0.f, sll = 0.f;
#pragma unroll 4
    for (int r = r0 + half; r < r0 + rpb; r += 2) {
        float v = X[r * DIM + c];
        sx += v; sxx += v * v;
        size_t idx = (size_t)r * DIM + c;
        float w = g_LxP[idx] + g_LxP[idx + (size_t)MTOT * DIM]
                + g_LxP[idx + 2 * (size_t)MTOT * DIM] + g_LxP[idx + 3 * (size_t)MTOT * DIM];
        g_LxP[idx] = w;
        sl += w; sll += w * w;
    }
    __shared__ float sh[256];
    const int b = blockIdx.x;
    sh[tid] = sx;  __syncthreads();
    if (tid < 128) g_partials[(0 * 128 + c) * STATS_BLOCKS + b] = sh[tid] + sh[tid + 128];
    __syncthreads();
    sh[tid] = sxx; __syncthreads();
    if (tid < 128) g_partials[(1 * 128 + c) * STATS_BLOCKS + b] = sh[tid] + sh[tid + 128];
    __syncthreads();
    sh[tid] = sl;  __syncthreads();
    if (tid < 128) g_partials[(2 * 128 + c) * STATS_BLOCKS + b] = sh[tid] + sh[tid + 128];
    __syncthreads();
    sh[tid] = sll; __syncthreads();
    if (tid < 128) g_partials[(3 * 128 + c) * STATS_BLOCKS + b] = sh[tid] + sh[tid + 128];
}

// ---------------- BN stats pass 2: warp/feature, contiguous reads -----------
__global__ __launch_bounds__(256) void stats_final(const float* __restrict__ gamma,
                                                   const float* __restrict__ beta) {
    const int warp = threadIdx.x >> 5;
    const int lane = threadIdx.x & 31;
    const int k = blockIdx.x * 8 + warp;          // 0..255
    const int base = (k < 128) ? 0 : 2;
    const int c = k & 127;
    const float* ps = g_partials + (size_t)(base * 128 + c) * STATS_BLOCKS;
    const float* pq = g_partials + (size_t)((base + 1) * 128 + c) * STATS_BLOCKS;
    float s = 0.f, ss = 0.f;
#pragma unroll
    for (int b = lane; b < STATS_BLOCKS; b += 32) {
        s  += ps[b];
        ss += pq[b];
    }
    s = warp_sum(s);
    ss = warp_sum(ss);
    if (lane == 0) {
        float mean = s / (float)MTOT;
        float var  = ss / (float)MTOT - mean * mean;
        float sc   = rsqrtf(var + EPSV) * gamma[k];
        g_scale[k] = sc;
        g_shift[k] = beta[k] - mean * sc;
    }
}

// ---------------- fold BN into linear weights: bf16 split + beff ------------
// grid 32 x 256. w'[j][k] = w[j][k]*scale[k] -> g_wBh/g_wBl [j][k].
__global__ __launch_bounds__(256) void weff_kernel(const float* __restrict__ w,
                                                   const float* __restrict__ b) {
    const int e0 = (blockIdx.x * 256 + threadIdx.x) * 4;   // over [j][k] row-major
    const int j = e0 >> 8;
    const int k0 = e0 & 255;
    float4 wv = *(const float4*)(w + j * 256 + k0);
    float4 sv = *(const float4*)(g_scale + k0);
    float p0 = wv.x * sv.x, p1 = wv.y * sv.y, p2 = wv.z * sv.z, p3 = wv.w * sv.w;
    __nv_bfloat162 h01 = __floats2bfloat162_rn(p0, p1);
    __nv_bfloat162 h23 = __floats2bfloat162_rn(p2, p3);
    __nv_bfloat162 l01 = __floats2bfloat162_rn(p0 - __low2float(h01), p1 - __high2float(h01));
    __nv_bfloat162 l23 = __floats2bfloat162_rn(p2 - __low2float(h23), p3 - __high2float(h23));
    *(uint2*)(g_wBh + j * 256 + k0) = make_uint2(*(uint32_t*)&h01, *(uint32_t*)&h23);
    *(uint2*)(g_wBl + j * 256 + k0) = make_uint2(*(uint32_t*)&l01, *(uint32_t*)&l23);

    if (blockIdx.x < 16) {
        const int warp = threadIdx.x >> 5;
        const int lane = threadIdx.x & 31;
        const int jo = blockIdx.x * 8 + warp;     // 0..127
        float s = 0.f;
        for (int kk = lane; kk < 256; kk += 32)
            s += g_shift[kk] * w[jo * 256 + kk];
        s = warp_sum(s);
        if (lane == 0) g_beff[jo] = b[jo] + s;
    }
}

// ---------------- HMMA linear: out = [X|Lx] @ w'^T + beff, fused epilogue ---
// 64 CTAs, M=128/CTA, N=128, K=256 (8 iters of BK=32).
// mode 0: v=elu(y) -> g_bufX2 (fp32) AND packed bf16 hi/lo -> g_Bh/g_Bl
// mode 1: v=y+resid -> dst
__global__ __launch_bounds__(256, 2) void linear_mma(int xsel,
                                                     const float* __restrict__ resid,
                                                     float* __restrict__ dst, int mode) {
    extern __shared__ char smem[];
    const int tid = threadIdx.x;
    const int lane = tid & 31;
    const int w = tid >> 5;
    const int wm = w >> 1;
    const int wn = w & 1;
    const int m0 = blockIdx.x * 128;

    const uint32_t sb = smem_u32(smem);
    const float* __restrict__ Xs = xsel ? g_bufX2 : g_bufX;

    const int a_row = wm * 32 + (lane & 7) + ((lane >> 3) & 1) * 8;
    const uint32_t aOff = (uint32_t)a_row * ROWB + ((lane >> 4) & 1) * 16;
    const int b_row = wn * 64 + (lane & 7) + ((lane >> 4) & 1) * 8;
    const uint32_t bOff = (uint32_t)b_row * ROWB + ((lane >> 3) & 1) * 16;

    const int grow = tid >> 1;
    const int gh = tid & 1;
    const __nv_bfloat16* Bhp = g_wBh + (size_t)grow * FEAT + gh * 16;
    const __nv_bfloat16* Blp = g_wBl + (size_t)grow * FEAT + gh * 16;
    const uint32_t aStOff = (uint32_t)grow * ROWB + gh * 32;

    float acc[2][8][4];
#pragma unroll
    for (int i = 0; i < 2; i++)
#pragma unroll
        for (int j = 0; j < 8; j++)
#pragma unroll
            for (int q = 0; q < 4; q++) acc[i][j][q] = 0.f;

    float4 ar[4];

    // A source pointer for stage t
    auto aPtr = [&](int t) -> const float* {
        int kk = t * 32 + gh * 16;
        return (kk < 128) ? (Xs + (size_t)(m0 + grow) * DIM + kk)
                          : (g_LxP + (size_t)(m0 + grow) * DIM + (kk - 128));
    };

    cpasync16(sb + 2 * OPSZ + aStOff,      Bhp);
    cpasync16(sb + 2 * OPSZ + aStOff + 16, Bhp + 8);
    cpasync16(sb + 3 * OPSZ + aStOff,      Blp);
    cpasync16(sb + 3 * OPSZ + aStOff + 16, Blp + 8);
    cp_commit();
    {
        const float* ap = aPtr(0);
#pragma unroll
        for (int i = 0; i < 4; i++) ar[i] = *(const float4*)(ap + 4 * i);
        char* sAh = smem + aStOff;
        char* sAl = smem + OPSZ + aStOff;
#pragma unroll
        for (int i = 0; i < 4; i++) {
            float4 v = ar[i];
            __nv_bfloat162 h01 = __floats2bfloat162_rn(v.x, v.y);
            __nv_bfloat162 h23 = __floats2bfloat162_rn(v.z, v.w);
            __nv_bfloat162 l01 = __floats2bfloat162_rn(v.x - __low2float(h01), v.y - __high2float(h01));
            __nv_bfloat162 l23 = __floats2bfloat162_rn(v.z - __low2float(h23), v.w - __high2float(h23));
            *(uint2*)(sAh + 8 * i) = make_uint2(*(uint32_t*)&h01, *(uint32_t*)&h23);
            *(uint2*)(sAl + 8 * i) = make_uint2(*(uint32_t*)&l01, *(uint32_t*)&l23);
        }
    }

    const int T = FEAT / 32;  // 8

    for (int t = 0; t < T; t++) {
        cp_wait0();
        __syncthreads();
        const int s = t & 1;
        const uint32_t sA = sb + s * STGSZ;
        const uint32_t nsBase = sb + (s ^ 1) * STGSZ;
        const bool more = (t + 1) < T;
        if (more) {
            const int off = (t + 1) * 32;
            cpasync16(nsBase + 2 * OPSZ + aStOff,      Bhp + off);
            cpasync16(nsBase + 2 * OPSZ + aStOff + 16, Bhp + off + 8);
            cpasync16(nsBase + 3 * OPSZ + aStOff,      Blp + off);
            cpasync16(nsBase + 3 * OPSZ + aStOff + 16, Blp + off + 8);
            cp_commit();
            const float* ap = aPtr(t + 1);
#pragma unroll
            for (int i = 0; i < 4; i++) ar[i] = *(const float4*)(ap + 4 * i);
        }

#pragma unroll
        for (int ks = 0; ks < 2; ks++) {
            const uint32_t kb = ks * 32;
            uint32_t Ah[2][4], Al[2][4];
#pragma unroll
            for (int mf = 0; mf < 2; mf++) {
                ldmx4(Ah[mf], sA + aOff + mf * (16 * ROWB) + kb);
                ldmx4(Al[mf], sA + OPSZ + aOff + mf * (16 * ROWB) + kb);
            }
#pragma unroll
            for (int qh = 0; qh < 2; qh++) {
                uint32_t Bh2[2][4], Bl2[2][4];
#pragma unroll
                for (int qq = 0; qq < 2; qq++) {
                    const int q = qh * 2 + qq;
                    ldmx4(Bh2[qq], sA + 2 * OPSZ + bOff + q * (16 * ROWB) + kb);
                    ldmx4(Bl2[qq], sA + 3 * OPSZ + bOff + q * (16 * ROWB) + kb);
                }
#pragma unroll
                for (int mf = 0; mf < 2; mf++)
#pragma unroll
                    for (int qq = 0; qq < 2; qq++)
#pragma unroll
                        for (int j = 0; j < 2; j++) {
                            const int nf = qh * 4 + qq * 2 + j;
                            const int rr = j * 2;
                            mma_bf16(acc[mf][nf], Ah[mf], Bh2[qq][rr], Bh2[qq][rr + 1]);
                            mma_bf16(acc[mf][nf], Ah[mf], Bl2[qq][rr], Bl2[qq][rr + 1]);
                            mma_bf16(acc[mf][nf], Al[mf], Bh2[qq][rr], Bh2[qq][rr + 1]);
                        }
            }
        }

        if (more) {
            char* other = smem + (s ^ 1) * STGSZ;
            char* sAh = other + aStOff;
            char* sAl = other + OPSZ + aStOff;
#pragma unroll
            for (int i = 0; i < 4; i++) {
                float4 v = ar[i];
                __nv_bfloat162 h01 = __floats2bfloat162_rn(v.x, v.y);
                __nv_bfloat162 h23 = __floats2bfloat162_rn(v.z, v.w);
                __nv_bfloat162 l01 = __floats2bfloat162_rn(v.x - __low2float(h01), v.y - __high2float(h01));
                __nv_bfloat162 l23 = __floats2bfloat162_rn(v.z - __low2float(h23), v.w - __high2float(h23));
                *(uint2*)(sAh + 8 * i) = make_uint2(*(uint32_t*)&h01, *(uint32_t*)&h23);
                *(uint2*)(sAl + 8 * i) = make_uint2(*(uint32_t*)&l01, *(uint32_t*)&l23);
            }
        }
    }

    // ---- epilogue ----
    const int g = lane >> 2, t4 = lane & 3;
#pragma unroll
    for (int mf = 0; mf < 2; mf++) {
        const int row0 = m0 + wm * 32 + mf * 16 + g;
#pragma unroll
        for (int nf = 0; nf < 8; nf++) {
            const int col = wn * 64 + nf * 8 + t4 * 2;
            float b0 = g_beff[col], b1 = g_beff[col + 1];
            float y0 = acc[mf][nf][0] + b0;
            float y1 = acc[mf][nf][1] + b1;
            float y2 = acc[mf][nf][2] + b0;
            float y3 = acc[mf][nf][3] + b1;
            if (mode == 0) {
                float v0 = eluf(y0), v1 = eluf(y1), v2 = eluf(y2), v3 = eluf(y3);
                *(float2*)(g_bufX2 + (size_t)row0 * DIM + col) = make_float2(v0, v1);
                *(float2*)(g_bufX2 + (size_t)(row0 + 8) * DIM + col) = make_float2(v2, v3);
                __nv_bfloat16 h, l;
                split_bf16(v0, h, l);
                g_Bh[(size_t)col * MTOT + row0] = h;       g_Bl[(size_t)col * MTOT + row0] = l;
                split_bf16(v1, h, l);
                g_Bh[(size_t)(col + 1) * MTOT + row0] = h; g_Bl[(size_t)(col + 1) * MTOT + row0] = l;
                split_bf16(v2, h, l);
                g_Bh[(size_t)col * MTOT + row0 + 8] = h;       g_Bl[(size_t)col * MTOT + row0 + 8] = l;
                split_bf16(v3, h, l);
                g_Bh[(size_t)(col + 1) * MTOT + row0 + 8] = h; g_Bl[(size_t)(col + 1) * MTOT + row0 + 8] = l;
            } else {
                float r0v = resid[(size_t)row0 * DIM + col];
                float r1v = resid[(size_t)row0 * DIM + col + 1];
                float r2v = resid[(size_t)(row0 + 8) * DIM + col];
                float r3v = resid[(size_t)(row0 + 8) * DIM + col + 1];
                *(float2*)(dst + (size_t)row0 * DIM + col) = make_float2(y0 + r0v, y1 + r1v);
                *(float2*)(dst + (size_t)(row0 + 8) * DIM + col) = make_float2(y2 + r2v, y3 + r3v);
            }
        }
    }
}

// ---------------- launch ----------------------------------------------------
extern "C" void kernel_launch(void* const* d_in, const int* in_sizes, int n_in,
                              void* d_out, int out_size) {
    const float* L      = (const float*)d_in[0];
    const float* inputs = (const float*)d_in[2];
    const float* bn0_g  = (const float*)d_in[3];
    const float* bn0_b  = (const float*)d_in[4];
    const float* fc0_w  = (const float*)d_in[5];
    const float* fc0_b  = (const float*)d_in[6];
    const float* bn1_g  = (const float*)d_in[7];
    const float* bn1_b  = (const float*)d_in[8];
    const float* fc1_w  = (const float*)d_in[9];
    const float* fc1_b  = (const float*)d_in[10];
    float* out = (float*)d_out;

    cudaFuncSetAttribute(sgemm_mma, cudaFuncAttributeMaxDynamicSharedMemorySize, SGEMM_SMEM);
    cudaFuncSetAttribute(linear_mma, cudaFuncAttributeMaxDynamicSharedMemorySize, SGEMM_SMEM);

    // ---- block 0 ----
    pack_kernel<<<128, 256>>>(inputs);
    sgemm_mma<<<256, 256, SGEMM_SMEM>>>(L);
    stats_partial<<<STATS_BLOCKS, 256>>>(0);
    stats_final<<<32, 256>>>(bn0_g, bn0_b);
    weff_kernel<<<32, 256>>>(fc0_w, fc0_b);
    linear_mma<<<64, 256, SGEMM_SMEM>>>(0, nullptr, nullptr, 0);  // also packs B for block 1

    // ---- block 1 ----
    sgemm_mma<<<256, 256, SGEMM_SMEM>>>(L);
    stats_partial<<<STATS_BLOCKS, 256>>>(1);
    stats_final<<<32, 256>>>(bn1_g, bn1_b);
    weff_kernel<<<32, 256>>>(fc1_w, fc1_b);
    linear_mma<<<64, 256, SGEMM_SMEM>>>(1, inputs, out, 1);
}

// round 8
// speedup vs baseline: 4.3364x; 1.0349x over previous
#include <cuda_runtime.h>
#include <cuda_bf16.h>
#include <math.h>
#include <stdint.h>

#define MTOT 8192
#define KDIM 8192
#define DIM 128
#define FEAT 256
#define EPSV 1e-5f
#define STATS_BLOCKS 512
#define NKSL 8

// ---------------- scratch (device globals; no allocs allowed) ----------------
__device__ float g_bufX [MTOT * DIM];        // activations entering a block (fp32)
__device__ float g_bufX2[MTOT * DIM];        // activations entering block 2 (fp32)
__device__ float g_LxP [NKSL * MTOT * DIM];  // partial L@x per K slice (slice 0 -> sum)
// B^T operand, bf16 hi/lo: row-major [feat 128][node 8192]
__device__ __nv_bfloat16 g_Bh[DIM * MTOT];
__device__ __nv_bfloat16 g_Bl[DIM * MTOT];
// partials transposed: [quad 0..3][feat 0..127][block]
__device__ float g_partials[4 * DIM * STATS_BLOCKS];
__device__ float g_scale[FEAT];
__device__ float g_shift[FEAT];
// BN-folded linear weights, bf16 split, row-major [j 128][k 256]
__device__ __nv_bfloat16 g_wBh[DIM * FEAT];
__device__ __nv_bfloat16 g_wBl[DIM * FEAT];
__device__ float g_beff[DIM];

// ---------------- helpers ----------------
__device__ __forceinline__ uint32_t smem_u32(const void* p) {
    uint32_t a;
    asm("{ .reg .u64 t; cvta.to.shared.u64 t, %1; cvt.u32.u64 %0, t; }" : "=r"(a) : "l"(p));
    return a;
}
__device__ __forceinline__ void ldmx4(uint32_t* r, uint32_t addr) {
    asm volatile("ldmatrix.sync.aligned.m8n8.x4.shared.b16 {%0,%1,%2,%3}, [%4];"
                 : "=r"(r[0]), "=r"(r[1]), "=r"(r[2]), "=r"(r[3]) : "r"(addr));
}
__device__ __forceinline__ void mma_bf16(float* d, const uint32_t* a, uint32_t b0, uint32_t b1) {
    asm volatile(
        "mma.sync.aligned.m16n8k16.row.col.f32.bf16.bf16.f32 "
        "{%0,%1,%2,%3}, {%4,%5,%6,%7}, {%8,%9}, {%0,%1,%2,%3};"
        : "+f"(d[0]), "+f"(d[1]), "+f"(d[2]), "+f"(d[3])
        : "r"(a[0]), "r"(a[1]), "r"(a[2]), "r"(a[3]), "r"(b0), "r"(b1));
}
__device__ __forceinline__ void cpasync16(uint32_t dst, const void* src) {
    asm volatile("cp.async.cg.shared.global [%0], [%1], 16;" :: "r"(dst), "l"(src));
}
__device__ __forceinline__ void cp_commit() { asm volatile("cp.async.commit_group;"); }
__device__ __forceinline__ void cp_wait0()  { asm volatile("cp.async.wait_group 0;" ::: "memory"); }

__device__ __forceinline__ float eluf(float v) { return v > 0.f ? v : expm1f(v); }

__device__ __forceinline__ float warp_sum(float v) {
#pragma unroll
    for (int o = 16; o > 0; o >>= 1) v += __shfl_xor_sync(0xFFFFFFFFu, v, o);
    return v;
}
__device__ __forceinline__ void split_bf16(float v, __nv_bfloat16& h, __nv_bfloat16& l) {
    h = __float2bfloat16(v);
    l = __float2bfloat16(v - __bfloat162float(h));
}

// ---------------- pack: inputs -> ELU -> g_bufX + B^T bf16 hi/lo ------------
__global__ __launch_bounds__(256) void pack_kernel(const float* __restrict__ src) {
    __shared__ float tile[128][65];   // [feat][node_local]
    const int tid = threadIdx.x;
    const int node0 = blockIdx.x * 64;

    const float4* sv = (const float4*)src + (size_t)node0 * 32;
    float4* xv = (float4*)g_bufX + (size_t)node0 * 32;
#pragma unroll
    for (int i = 0; i < 8; i++) {
        int idx = tid + 256 * i;
        int node = idx >> 5;
        int fq = idx & 31;
        float4 v = sv[idx];
        v.x = eluf(v.x); v.y = eluf(v.y); v.z = eluf(v.z); v.w = eluf(v.w);
        xv[idx] = v;
        tile[fq * 4 + 0][node] = v.x;
        tile[fq * 4 + 1][node] = v.y;
        tile[fq * 4 + 2][node] = v.z;
        tile[fq * 4 + 3][node] = v.w;
    }
    __syncthreads();

    const int feat = tid >> 1;
    const int h = tid & 1;
    const float* r = &tile[feat][h * 32];
    uint32_t hi[16], lo[16];
#pragma unroll
    for (int j = 0; j < 16; j++) {
        float a = r[2 * j], b = r[2 * j + 1];
        __nv_bfloat162 hb = __floats2bfloat162_rn(a, b);
        float ha = __low2float(hb), hbv = __high2float(hb);
        __nv_bfloat162 lb = __floats2bfloat162_rn(a - ha, b - hbv);
        hi[j] = *(uint32_t*)&hb;
        lo[j] = *(uint32_t*)&lb;
    }
    uint4* oh = (uint4*)(g_Bh + (size_t)feat * MTOT + node0 + h * 32);
    uint4* ol = (uint4*)(g_Bl + (size_t)feat * MTOT + node0 + h * 32);
#pragma unroll
    for (int blk = 0; blk < 4; blk++) {
        oh[blk] = make_uint4(hi[4 * blk], hi[4 * blk + 1], hi[4 * blk + 2], hi[4 * blk + 3]);
        ol[blk] = make_uint4(lo[4 * blk], lo[4 * blk + 1], lo[4 * blk + 2], lo[4 * blk + 3]);
    }
}

// ---------------- split-bf16 HMMA GEMM: LxP[ksl] = L[:,slice] @ X[slice] ----
// 512 CTAs = 64 M-tiles x 8 K-slices, 2 CTAs/SM. CTA: M=128,N=128,BK=32,K=1024.
#define ROWB 80
#define OPSZ 10240
#define STGSZ 40960
#define SGEMM_SMEM (2 * STGSZ)

__global__ __launch_bounds__(256, 2) void sgemm_mma(const float* __restrict__ L) {
    extern __shared__ char smem[];
    const int tid = threadIdx.x;
    const int lane = tid & 31;
    const int w = tid >> 5;
    const int wm = w >> 1;
    const int wn = w & 1;
    const int mtile = blockIdx.x >> 3;
    const int ksl = blockIdx.x & 7;
    const int m0 = mtile * 128;
    const int kc0 = ksl * 1024;

    const uint32_t sb = smem_u32(smem);

    const int a_row = wm * 32 + (lane & 7) + ((lane >> 3) & 1) * 8;
    const uint32_t aOff = (uint32_t)a_row * ROWB + ((lane >> 4) & 1) * 16;
    const int b_row = wn * 64 + (lane & 7) + ((lane >> 4) & 1) * 8;
    const uint32_t bOff = (uint32_t)b_row * ROWB + ((lane >> 3) & 1) * 16;

    const int grow = tid >> 1;
    const int gh = tid & 1;
    const float* Ap = L + (size_t)(m0 + grow) * KDIM + kc0 + gh * 16;
    const __nv_bfloat16* Bhp = g_Bh + (size_t)grow * MTOT + kc0 + gh * 16;
    const __nv_bfloat16* Blp = g_Bl + (size_t)grow * MTOT + kc0 + gh * 16;
    const uint32_t aStOff = (uint32_t)grow * ROWB + gh * 32;

    float acc[2][8][4];
#pragma unroll
    for (int i = 0; i < 2; i++)
#pragma unroll
        for (int j = 0; j < 8; j++)
#pragma unroll
            for (int q = 0; q < 4; q++) acc[i][j][q] = 0.f;

    float4 ar[4];

    cpasync16(sb + 2 * OPSZ + aStOff,      Bhp);
    cpasync16(sb + 2 * OPSZ + aStOff + 16, Bhp + 8);
    cpasync16(sb + 3 * OPSZ + aStOff,      Blp);
    cpasync16(sb + 3 * OPSZ + aStOff + 16, Blp + 8);
    cp_commit();
#pragma unroll
    for (int i = 0; i < 4; i++) ar[i] = *(const float4*)(Ap + 4 * i);
    {
        char* sAh = smem + aStOff;
        char* sAl = smem + OPSZ + aStOff;
#pragma unroll
        for (int i = 0; i < 4; i++) {
            float4 v = ar[i];
            __nv_bfloat162 h01 = __floats2bfloat162_rn(v.x, v.y);
            __nv_bfloat162 h23 = __floats2bfloat162_rn(v.z, v.w);
            __nv_bfloat162 l01 = __floats2bfloat162_rn(v.x - __low2float(h01), v.y - __high2float(h01));
            __nv_bfloat162 l23 = __floats2bfloat162_rn(v.z - __low2float(h23), v.w - __high2float(h23));
            *(uint2*)(sAh + 8 * i) = make_uint2(*(uint32_t*)&h01, *(uint32_t*)&h23);
            *(uint2*)(sAl + 8 * i) = make_uint2(*(uint32_t*)&l01, *(uint32_t*)&l23);
        }
    }

    const int T = 1024 / 32;  // 32

    for (int t = 0; t < T; t++) {
        cp_wait0();
        __syncthreads();
        const int s = t & 1;
        const uint32_t sA = sb + s * STGSZ;
        const uint32_t nsBase = sb + (s ^ 1) * STGSZ;
        const bool more = (t + 1) < T;
        if (more) {
            const int off = (t + 1) * 32;
            cpasync16(nsBase + 2 * OPSZ + aStOff,      Bhp + off);
            cpasync16(nsBase + 2 * OPSZ + aStOff + 16, Bhp + off + 8);
            cpasync16(nsBase + 3 * OPSZ + aStOff,      Blp + off);
            cpasync16(nsBase + 3 * OPSZ + aStOff + 16, Blp + off + 8);
            cp_commit();
#pragma unroll
            for (int i = 0; i < 4; i++) ar[i] = *(const float4*)(Ap + off + 4 * i);
        }

#pragma unroll
        for (int ks = 0; ks < 2; ks++) {
            const uint32_t kb = ks * 32;
            uint32_t Ah[2][4], Al[2][4];
#pragma unroll
            for (int mf = 0; mf < 2; mf++) {
                ldmx4(Ah[mf], sA + aOff + mf * (16 * ROWB) + kb);
                ldmx4(Al[mf], sA + OPSZ + aOff + mf * (16 * ROWB) + kb);
            }
#pragma unroll
            for (int qh = 0; qh < 2; qh++) {
                uint32_t Bh2[2][4], Bl2[2][4];
#pragma unroll
                for (int qq = 0; qq < 2; qq++) {
                    const int q = qh * 2 + qq;
                    ldmx4(Bh2[qq], sA + 2 * OPSZ + bOff + q * (16 * ROWB) + kb);
                    ldmx4(Bl2[qq], sA + 3 * OPSZ + bOff + q * (16 * ROWB) + kb);
                }
#pragma unroll
                for (int mf = 0; mf < 2; mf++)
#pragma unroll
                    for (int qq = 0; qq < 2; qq++)
#pragma unroll
                        for (int j = 0; j < 2; j++) {
                            const int nf = qh * 4 + qq * 2 + j;
                            const int rr = j * 2;
                            mma_bf16(acc[mf][nf], Ah[mf], Bh2[qq][rr], Bh2[qq][rr + 1]);
                            mma_bf16(acc[mf][nf], Ah[mf], Bl2[qq][rr], Bl2[qq][rr + 1]);
                            mma_bf16(acc[mf][nf], Al[mf], Bh2[qq][rr], Bh2[qq][rr + 1]);
                        }
            }
        }

        if (more) {
            char* other = smem + (s ^ 1) * STGSZ;
            char* sAh = other + aStOff;
            char* sAl = other + OPSZ + aStOff;
#pragma unroll
            for (int i = 0; i < 4; i++) {
                float4 v = ar[i];
                __nv_bfloat162 h01 = __floats2bfloat162_rn(v.x, v.y);
                __nv_bfloat162 h23 = __floats2bfloat162_rn(v.z, v.w);
                __nv_bfloat162 l01 = __floats2bfloat162_rn(v.x - __low2float(h01), v.y - __high2float(h01));
                __nv_bfloat162 l23 = __floats2bfloat162_rn(v.z - __low2float(h23), v.w - __high2float(h23));
                *(uint2*)(sAh + 8 * i) = make_uint2(*(uint32_t*)&h01, *(uint32_t*)&h23);
                *(uint2*)(sAl + 8 * i) = make_uint2(*(uint32_t*)&l01, *(uint32_t*)&l23);
            }
        }
    }

    float* outb = g_LxP + (size_t)ksl * (MTOT * DIM);
    const int g = lane >> 2, t4 = lane & 3;
#pragma unroll
    for (int mf = 0; mf < 2; mf++) {
        const int row0 = m0 + wm * 32 + mf * 16 + g;
#pragma unroll
        for (int nf = 0; nf < 8; nf++) {
            const int col = wn * 64 + nf * 8 + t4 * 2;
            *(float2*)(outb + (size_t)row0 * DIM + col) =
                make_float2(acc[mf][nf][0], acc[mf][nf][1]);
            *(float2*)(outb + (size_t)(row0 + 8) * DIM + col) =
                make_float2(acc[mf][nf][2], acc[mf][nf][3]);
        }
    }
}

// ---------------- BN stats pass 1 + K-split fold (transposed partials) ------
__global__ __launch_bounds__(256) void stats_partial(int xsel) {
    const float* __restrict__ X = xsel ? g_bufX2 : g_bufX;
    const int tid = threadIdx.x;
    const int c = tid & 127;
    const int half = tid >> 7;
    const int rpb = MTOT / STATS_BLOCKS;   // 16
    const int r0 = blockIdx.x * rpb;

    float sx = 0.f, sxx = 0.f, sl = 0.f, sll = 0.f;
#pragma unroll 4
    for (int r = r0 + half; r < r0 + rpb; r += 2) {
        float v = X[r * DIM + c];
        sx += v; sxx += v * v;
        size_t idx = (size_t)r * DIM + c;
        float w = 0.f;
#pragma unroll
        for (int q = 0; q < NKSL; q++) w += g_LxP[idx + (size_t)q * MTOT * DIM];
        g_LxP[idx] = w;
        sl += w; sll += w * w;
    }
    __shared__ float sh[256];
    const int b = blockIdx.x;
    sh[tid] = sx;  __syncthreads();
    if (tid < 128) g_partials[(0 * 128 + c) * STATS_BLOCKS + b] = sh[tid] + sh[tid + 128];
    __syncthreads();
    sh[tid] = sxx; __syncthreads();
    if (tid < 128) g_partials[(1 * 128 + c) * STATS_BLOCKS + b] = sh[tid] + sh[tid + 128];
    __syncthreads();
    sh[tid] = sl;  __syncthreads();
    if (tid < 128) g_partials[(2 * 128 + c) * STATS_BLOCKS + b] = sh[tid] + sh[tid + 128];
    __syncthreads();
    sh[tid] = sll; __syncthreads();
    if (tid < 128) g_partials[(3 * 128 + c) * STATS_BLOCKS + b] = sh[tid] + sh[tid + 128];
}

// ---------------- BN stats pass 2: warp/feature, contiguous reads -----------
__global__ __launch_bounds__(256) void stats_final(const float* __restrict__ gamma,
                                                   const float* __restrict__ beta) {
    const int warp = threadIdx.x >> 5;
    const int lane = threadIdx.x & 31;
    const int k = blockIdx.x * 8 + warp;          // 0..255
    const int base = (k < 128) ? 0 : 2;
    const int c = k & 127;
    const float* ps = g_partials + (size_t)(base * 128 + c) * STATS_BLOCKS;
    const float* pq = g_partials + (size_t)((base + 1) * 128 + c) * STATS_BLOCKS;
    float s = 0.f, ss = 0.f;
#pragma unroll
    for (int b = lane; b < STATS_BLOCKS; b += 32) {
        s  += ps[b];
        ss += pq[b];
    }
    s = warp_sum(s);
    ss = warp_sum(ss);
    if (lane == 0) {
        float mean = s / (float)MTOT;
        float var  = ss / (float)MTOT - mean * mean;
        float sc   = rsqrtf(var + EPSV) * gamma[k];
        g_scale[k] = sc;
        g_shift[k] = beta[k] - mean * sc;
    }
}

// ---------------- fold BN into linear weights: bf16 split + beff ------------
__global__ __launch_bounds__(256) void weff_kernel(const float* __restrict__ w,
                                                   const float* __restrict__ b) {
    const int e0 = (blockIdx.x * 256 + threadIdx.x) * 4;   // over [j][k] row-major
    const int j = e0 >> 8;
    const int k0 = e0 & 255;
    float4 wv = *(const float4*)(w + j * 256 + k0);
    float4 sv = *(const float4*)(g_scale + k0);
    float p0 = wv.x * sv.x, p1 = wv.y * sv.y, p2 = wv.z * sv.z, p3 = wv.w * sv.w;
    __nv_bfloat162 h01 = __floats2bfloat162_rn(p0, p1);
    __nv_bfloat162 h23 = __floats2bfloat162_rn(p2, p3);
    __nv_bfloat162 l01 = __floats2bfloat162_rn(p0 - __low2float(h01), p1 - __high2float(h01));
    __nv_bfloat162 l23 = __floats2bfloat162_rn(p2 - __low2float(h23), p3 - __high2float(h23));
    *(uint2*)(g_wBh + j * 256 + k0) = make_uint2(*(uint32_t*)&h01, *(uint32_t*)&h23);
    *(uint2*)(g_wBl + j * 256 + k0) = make_uint2(*(uint32_t*)&l01, *(uint32_t*)&l23);

    if (blockIdx.x < 16) {
        const int warp = threadIdx.x >> 5;
        const int lane = threadIdx.x & 31;
        const int jo = blockIdx.x * 8 + warp;     // 0..127
        float s = 0.f;
        for (int kk = lane; kk < 256; kk += 32)
            s += g_shift[kk] * w[jo * 256 + kk];
        s = warp_sum(s);
        if (lane == 0) g_beff[jo] = b[jo] + s;
    }
}

// ---------------- HMMA linear: out = [X|Lx] @ w'^T + beff, fused epilogue ---
__global__ __launch_bounds__(256, 2) void linear_mma(int xsel,
                                                     const float* __restrict__ resid,
                                                     float* __restrict__ dst, int mode) {
    extern __shared__ char smem[];
    const int tid = threadIdx.x;
    const int lane = tid & 31;
    const int w = tid >> 5;
    const int wm = w >> 1;
    const int wn = w & 1;
    const int m0 = blockIdx.x * 128;

    const uint32_t sb = smem_u32(smem);
    const float* __restrict__ Xs = xsel ? g_bufX2 : g_bufX;

    const int a_row = wm * 32 + (lane & 7) + ((lane >> 3) & 1) * 8;
    const uint32_t aOff = (uint32_t)a_row * ROWB + ((lane >> 4) & 1) * 16;
    const int b_row = wn * 64 + (lane & 7) + ((lane >> 4) & 1) * 8;
    const uint32_t bOff = (uint32_t)b_row * ROWB + ((lane >> 3) & 1) * 16;

    const int grow = tid >> 1;
    const int gh = tid & 1;
    const __nv_bfloat16* Bhp = g_wBh + (size_t)grow * FEAT + gh * 16;
    const __nv_bfloat16* Blp = g_wBl + (size_t)grow * FEAT + gh * 16;
    const uint32_t aStOff = (uint32_t)grow * ROWB + gh * 32;

    float acc[2][8][4];
#pragma unroll
    for (int i = 0; i < 2; i++)
#pragma unroll
        for (int j = 0; j < 8; j++)
#pragma unroll
            for (int q = 0; q < 4; q++) acc[i][j][q] = 0.f;

    float4 ar[4];

    auto aPtr = [&](int t) -> const float* {
        int kk = t * 32 + gh * 16;
        return (kk < 128) ? (Xs + (size_t)(m0 + grow) * DIM + kk)
                          : (g_LxP + (size_t)(m0 + grow) * DIM + (kk - 128));
    };

    cpasync16(sb + 2 * OPSZ + aStOff,      Bhp);
    cpasync16(sb + 2 * OPSZ + aStOff + 16, Bhp + 8);
    cpasync16(sb + 3 * OPSZ + aStOff,      Blp);
    cpasync16(sb + 3 * OPSZ + aStOff + 16, Blp + 8);
    cp_commit();
    {
        const float* ap = aPtr(0);
#pragma unroll
        for (int i = 0; i < 4; i++) ar[i] = *(const float4*)(ap + 4 * i);
        char* sAh = smem + aStOff;
        char* sAl = smem + OPSZ + aStOff;
#pragma unroll
        for (int i = 0; i < 4; i++) {
            float4 v = ar[i];
            __nv_bfloat162 h01 = __floats2bfloat162_rn(v.x, v.y);
            __nv_bfloat162 h23 = __floats2bfloat162_rn(v.z, v.w);
            __nv_bfloat162 l01 = __floats2bfloat162_rn(v.x - __low2float(h01), v.y - __high2float(h01));
            __nv_bfloat162 l23 = __floats2bfloat162_rn(v.z - __low2float(h23), v.w - __high2float(h23));
            *(uint2*)(sAh + 8 * i) = make_uint2(*(uint32_t*)&h01, *(uint32_t*)&h23);
            *(uint2*)(sAl + 8 * i) = make_uint2(*(uint32_t*)&l01, *(uint32_t*)&l23);
        }
    }

    const int T = FEAT / 32;  // 8

    for (int t = 0; t < T; t++) {
        cp_wait0();
        __syncthreads();
        const int s = t & 1;
        const uint32_t sA = sb + s * STGSZ;
        const uint32_t nsBase = sb + (s ^ 1) * STGSZ;
        const bool more = (t + 1) < T;
        if (more) {
            const int off = (t + 1) * 32;
            cpasync16(nsBase + 2 * OPSZ + aStOff,      Bhp + off);
            cpasync16(nsBase + 2 * OPSZ + aStOff + 16, Bhp + off + 8);
            cpasync16(nsBase + 3 * OPSZ + aStOff,      Blp + off);
            cpasync16(nsBase + 3 * OPSZ + aStOff + 16, Blp + off + 8);
            cp_commit();
            const float* ap = aPtr(t + 1);
#pragma unroll
            for (int i = 0; i < 4; i++) ar[i] = *(const float4*)(ap + 4 * i);
        }

#pragma unroll
        for (int ks = 0; ks < 2; ks++) {
            const uint32_t kb = ks * 32;
            uint32_t Ah[2][4], Al[2][4];
#pragma unroll
            for (int mf = 0; mf < 2; mf++) {
                ldmx4(Ah[mf], sA + aOff + mf * (16 * ROWB) + kb);
                ldmx4(Al[mf], sA + OPSZ + aOff + mf * (16 * ROWB) + kb);
            }
#pragma unroll
            for (int qh = 0; qh < 2; qh++) {
                uint32_t Bh2[2][4], Bl2[2][4];
#pragma unroll
                for (int qq = 0; qq < 2; qq++) {
                    const int q = qh * 2 + qq;
                    ldmx4(Bh2[qq], sA + 2 * OPSZ + bOff + q * (16 * ROWB) + kb);
                    ldmx4(Bl2[qq], sA + 3 * OPSZ + bOff + q * (16 * ROWB) + kb);
                }
#pragma unroll
                for (int mf = 0; mf < 2; mf++)
#pragma unroll
                    for (int qq = 0; qq < 2; qq++)
#pragma unroll
                        for (int j = 0; j < 2; j++) {
                            const int nf = qh * 4 + qq * 2 + j;
                            const int rr = j * 2;
                            mma_bf16(acc[mf][nf], Ah[mf], Bh2[qq][rr], Bh2[qq][rr + 1]);
                            mma_bf16(acc[mf][nf], Ah[mf], Bl2[qq][rr], Bl2[qq][rr + 1]);
                            mma_bf16(acc[mf][nf], Al[mf], Bh2[qq][rr], Bh2[qq][rr + 1]);
                        }
            }
        }

        if (more) {
            char* other = smem + (s ^ 1) * STGSZ;
            char* sAh = other + aStOff;
            char* sAl = other + OPSZ + aStOff;
#pragma unroll
            for (int i = 0; i < 4; i++) {
                float4 v = ar[i];
                __nv_bfloat162 h01 = __floats2bfloat162_rn(v.x, v.y);
                __nv_bfloat162 h23 = __floats2bfloat162_rn(v.z, v.w);
                __nv_bfloat162 l01 = __floats2bfloat162_rn(v.x - __low2float(h01), v.y - __high2float(h01));
                __nv_bfloat162 l23 = __floats2bfloat162_rn(v.z - __low2float(h23), v.w - __high2float(h23));
                *(uint2*)(sAh + 8 * i) = make_uint2(*(uint32_t*)&h01, *(uint32_t*)&h23);
                *(uint2*)(sAl + 8 * i) = make_uint2(*(uint32_t*)&l01, *(uint32_t*)&l23);
            }
        }
    }

    const int g = lane >> 2, t4 = lane & 3;
#pragma unroll
    for (int mf = 0; mf < 2; mf++) {
        const int row0 = m0 + wm * 32 + mf * 16 + g;
#pragma unroll
        for (int nf = 0; nf < 8; nf++) {
            const int col = wn * 64 + nf * 8 + t4 * 2;
            float b0 = g_beff[col], b1 = g_beff[col + 1];
            float y0 = acc[mf][nf][0] + b0;
            float y1 = acc[mf][nf][1] + b1;
            float y2 = acc[mf][nf][2] + b0;
            float y3 = acc[mf][nf][3] + b1;
            if (mode == 0) {
                float v0 = eluf(y0), v1 = eluf(y1), v2 = eluf(y2), v3 = eluf(y3);
                *(float2*)(g_bufX2 + (size_t)row0 * DIM + col) = make_float2(v0, v1);
                *(float2*)(g_bufX2 + (size_t)(row0 + 8) * DIM + col) = make_float2(v2, v3);
                __nv_bfloat16 h, l;
                split_bf16(v0, h, l);
                g_Bh[(size_t)col * MTOT + row0] = h;       g_Bl[(size_t)col * MTOT + row0] = l;
                split_bf16(v1, h, l);
                g_Bh[(size_t)(col + 1) * MTOT + row0] = h; g_Bl[(size_t)(col + 1) * MTOT + row0] = l;
                split_bf16(v2, h, l);
                g_Bh[(size_t)col * MTOT + row0 + 8] = h;       g_Bl[(size_t)col * MTOT + row0 + 8] = l;
                split_bf16(v3, h, l);
                g_Bh[(size_t)(col + 1) * MTOT + row0 + 8] = h; g_Bl[(size_t)(col + 1) * MTOT + row0 + 8] = l;
            } else {
                float r0v = resid[(size_t)row0 * DIM + col];
                float r1v = resid[(size_t)row0 * DIM + col + 1];
                float r2v = resid[(size_t)(row0 + 8) * DIM + col];
                float r3v = resid[(size_t)(row0 + 8) * DIM + col + 1];
                *(float2*)(dst + (size_t)row0 * DIM + col) = make_float2(y0 + r0v, y1 + r1v);
                *(float2*)(dst + (size_t)(row0 + 8) * DIM + col) = make_float2(y2 + r2v, y3 + r3v);
            }
        }
    }
}

// ---------------- launch ----------------------------------------------------
extern "C" void kernel_launch(void* const* d_in, const int* in_sizes, int n_in,
                              void* d_out, int out_size) {
    const float* L      = (const float*)d_in[0];
    const float* inputs = (const float*)d_in[2];
    const float* bn0_g  = (const float*)d_in[3];
    const float* bn0_b  = (const float*)d_in[4];
    const float* fc0_w  = (const float*)d_in[5];
    const float* fc0_b  = (const float*)d_in[6];
    const float* bn1_g  = (const float*)d_in[7];
    const float* bn1_b  = (const float*)d_in[8];
    const float* fc1_w  = (const float*)d_in[9];
    const float* fc1_b  = (const float*)d_in[10];
    float* out = (float*)d_out;

    cudaFuncSetAttribute(sgemm_mma, cudaFuncAttributeMaxDynamicSharedMemorySize, SGEMM_SMEM);
    cudaFuncSetAttribute(linear_mma, cudaFuncAttributeMaxDynamicSharedMemorySize, SGEMM_SMEM);

    // ---- block 0 ----
    pack_kernel<<<128, 256>>>(inputs);
    sgemm_mma<<<512, 256, SGEMM_SMEM>>>(L);
    stats_partial<<<STATS_BLOCKS, 256>>>(0);
    stats_final<<<32, 256>>>(bn0_g, bn0_b);
    weff_kernel<<<32, 256>>>(fc0_w, fc0_b);
    linear_mma<<<64, 256, SGEMM_SMEM>>>(0, nullptr, nullptr, 0);  // also packs B for block 1

    // ---- block 1 ----
    sgemm_mma<<<512, 256, SGEMM_SMEM>>>(L);
    stats_partial<<<STATS_BLOCKS, 256>>>(1);
    stats_final<<<32, 256>>>(bn1_g, bn1_b);
    weff_kernel<<<32, 256>>>(fc1_w, fc1_b);
    linear_mma<<<64, 256, SGEMM_SMEM>>>(1, inputs, out, 1);
}

// round 10
// speedup vs baseline: 4.5526x; 1.0499x over previous
#include <cuda_runtime.h>
#include <cuda_bf16.h>
#include <math.h>
#include <stdint.h>

#define MTOT 8192
#define KDIM 8192
#define DIM 128
#define FEAT 256
#define EPSV 1e-5f
#define STATS_BLOCKS 512
#define NKSL 8

// ---------------- scratch (device globals; no allocs allowed) ----------------
__device__ float g_bufX [MTOT * DIM];
__device__ float g_bufX2[MTOT * DIM];
__device__ float g_LxP [NKSL * MTOT * DIM];  // K-slice partials (slice 0 -> folded sum)
__device__ __nv_bfloat16 g_Bh[DIM * MTOT];   // B^T bf16 hi [feat][node]
__device__ __nv_bfloat16 g_Bl[DIM * MTOT];
__device__ float g_partials[4 * DIM * STATS_BLOCKS];  // [quad][feat][block]
__device__ float g_scale[FEAT];
__device__ float g_shift[FEAT];
__device__ __nv_bfloat16 g_wBh[DIM * FEAT];  // folded weights bf16 [j][k]
__device__ __nv_bfloat16 g_wBl[DIM * FEAT];
__device__ float g_beff[DIM];

// ---------------- helpers ----------------
__device__ __forceinline__ uint32_t smem_u32(const void* p) {
    uint32_t a;
    asm("{ .reg .u64 t; cvta.to.shared.u64 t, %1; cvt.u32.u64 %0, t; }" : "=r"(a) : "l"(p));
    return a;
}
__device__ __forceinline__ void ldmx4(uint32_t* r, uint32_t addr) {
    asm volatile("ldmatrix.sync.aligned.m8n8.x4.shared.b16 {%0,%1,%2,%3}, [%4];"
                 : "=r"(r[0]), "=r"(r[1]), "=r"(r[2]), "=r"(r[3]) : "r"(addr));
}
__device__ __forceinline__ void mma_bf16(float* d, const uint32_t* a, uint32_t b0, uint32_t b1) {
    asm volatile(
        "mma.sync.aligned.m16n8k16.row.col.f32.bf16.bf16.f32 "
        "{%0,%1,%2,%3}, {%4,%5,%6,%7}, {%8,%9}, {%0,%1,%2,%3};"
        : "+f"(d[0]), "+f"(d[1]), "+f"(d[2]), "+f"(d[3])
        : "r"(a[0]), "r"(a[1]), "r"(a[2]), "r"(a[3]), "r"(b0), "r"(b1));
}
__device__ __forceinline__ void cpasync16(uint32_t dst, const void* src) {
    asm volatile("cp.async.cg.shared.global [%0], [%1], 16;" :: "r"(dst), "l"(src));
}
__device__ __forceinline__ void cp_commit() { asm volatile("cp.async.commit_group;"); }
__device__ __forceinline__ void cp_wait0()  { asm volatile("cp.async.wait_group 0;" ::: "memory"); }

__device__ __forceinline__ float eluf(float v) { return v > 0.f ? v : expm1f(v); }

__device__ __forceinline__ float warp_sum(float v) {
#pragma unroll
    for (int o = 16; o > 0; o >>= 1) v += __shfl_xor_sync(0xFFFFFFFFu, v, o);
    return v;
}
__device__ __forceinline__ void split_bf16(float v, __nv_bfloat16& h, __nv_bfloat16& l) {
    h = __float2bfloat16(v);
    l = __float2bfloat16(v - __bfloat162float(h));
}

// ---------------- pack: inputs -> ELU -> g_bufX + B^T bf16 hi/lo ------------
__global__ __launch_bounds__(256) void pack_kernel(const float* __restrict__ src) {
    __shared__ float tile[128][65];
    const int tid = threadIdx.x;
    const int node0 = blockIdx.x * 64;

    const float4* sv = (const float4*)src + (size_t)node0 * 32;
    float4* xv = (float4*)g_bufX + (size_t)node0 * 32;
#pragma unroll
    for (int i = 0; i < 8; i++) {
        int idx = tid + 256 * i;
        int node = idx >> 5;
        int fq = idx & 31;
        float4 v = sv[idx];
        v.x = eluf(v.x); v.y = eluf(v.y); v.z = eluf(v.z); v.w = eluf(v.w);
        xv[idx] = v;
        tile[fq * 4 + 0][node] = v.x;
        tile[fq * 4 + 1][node] = v.y;
        tile[fq * 4 + 2][node] = v.z;
        tile[fq * 4 + 3][node] = v.w;
    }
    __syncthreads();

    const int feat = tid >> 1;
    const int h = tid & 1;
    const float* r = &tile[feat][h * 32];
    uint32_t hi[16], lo[16];
#pragma unroll
    for (int j = 0; j < 16; j++) {
        float a = r[2 * j], b = r[2 * j + 1];
        __nv_bfloat162 hb = __floats2bfloat162_rn(a, b);
        float ha = __low2float(hb), hbv = __high2float(hb);
        __nv_bfloat162 lb = __floats2bfloat162_rn(a - ha, b - hbv);
        hi[j] = *(uint32_t*)&hb;
        lo[j] = *(uint32_t*)&lb;
    }
    uint4* oh = (uint4*)(g_Bh + (size_t)feat * MTOT + node0 + h * 32);
    uint4* ol = (uint4*)(g_Bl + (size_t)feat * MTOT + node0 + h * 32);
#pragma unroll
    for (int blk = 0; blk < 4; blk++) {
        oh[blk] = make_uint4(hi[4 * blk], hi[4 * blk + 1], hi[4 * blk + 2], hi[4 * blk + 3]);
        ol[blk] = make_uint4(lo[4 * blk], lo[4 * blk + 1], lo[4 * blk + 2], lo[4 * blk + 3]);
    }
}

// ---------------- split-bf16 HMMA GEMM (unchanged core) ---------------------
#define ROWB 80
#define OPSZ 10240
#define STGSZ 40960
#define SGEMM_SMEM (2 * STGSZ)

__global__ __launch_bounds__(256, 2) void sgemm_mma(const float* __restrict__ L) {
    extern __shared__ char smem[];
    const int tid = threadIdx.x;
    const int lane = tid & 31;
    const int w = tid >> 5;
    const int wm = w >> 1;
    const int wn = w & 1;
    const int mtile = blockIdx.x >> 3;
    const int ksl = blockIdx.x & 7;
    const int m0 = mtile * 128;
    const int kc0 = ksl * 1024;

    const uint32_t sb = smem_u32(smem);

    const int a_row = wm * 32 + (lane & 7) + ((lane >> 3) & 1) * 8;
    const uint32_t aOff = (uint32_t)a_row * ROWB + ((lane >> 4) & 1) * 16;
    const int b_row = wn * 64 + (lane & 7) + ((lane >> 4) & 1) * 8;
    const uint32_t bOff = (uint32_t)b_row * ROWB + ((lane >> 3) & 1) * 16;

    const int grow = tid >> 1;
    const int gh = tid & 1;
    const float* Ap = L + (size_t)(m0 + grow) * KDIM + kc0 + gh * 16;
    const __nv_bfloat16* Bhp = g_Bh + (size_t)grow * MTOT + kc0 + gh * 16;
    const __nv_bfloat16* Blp = g_Bl + (size_t)grow * MTOT + kc0 + gh * 16;
    const uint32_t aStOff = (uint32_t)grow * ROWB + gh * 32;

    float acc[2][8][4];
#pragma unroll
    for (int i = 0; i < 2; i++)
#pragma unroll
        for (int j = 0; j < 8; j++)
#pragma unroll
            for (int q = 0; q < 4; q++) acc[i][j][q] = 0.f;

    float4 ar[4];

    cpasync16(sb + 2 * OPSZ + aStOff,      Bhp);
    cpasync16(sb + 2 * OPSZ + aStOff + 16, Bhp + 8);
    cpasync16(sb + 3 * OPSZ + aStOff,      Blp);
    cpasync16(sb + 3 * OPSZ + aStOff + 16, Blp + 8);
    cp_commit();
#pragma unroll
    for (int i = 0; i < 4; i++) ar[i] = *(const float4*)(Ap + 4 * i);
    {
        char* sAh = smem + aStOff;
        char* sAl = smem + OPSZ + aStOff;
#pragma unroll
        for (int i = 0; i < 4; i++) {
            float4 v = ar[i];
            __nv_bfloat162 h01 = __floats2bfloat162_rn(v.x, v.y);
            __nv_bfloat162 h23 = __floats2bfloat162_rn(v.z, v.w);
            __nv_bfloat162 l01 = __floats2bfloat162_rn(v.x - __low2float(h01), v.y - __high2float(h01));
            __nv_bfloat162 l23 = __floats2bfloat162_rn(v.z - __low2float(h23), v.w - __high2float(h23));
            *(uint2*)(sAh + 8 * i) = make_uint2(*(uint32_t*)&h01, *(uint32_t*)&h23);
            *(uint2*)(sAl + 8 * i) = make_uint2(*(uint32_t*)&l01, *(uint32_t*)&l23);
        }
    }

    const int T = 1024 / 32;  // 32

    for (int t = 0; t < T; t++) {
        cp_wait0();
        __syncthreads();
        const int s = t & 1;
        const uint32_t sA = sb + s * STGSZ;
        const uint32_t nsBase = sb + (s ^ 1) * STGSZ;
        const bool more = (t + 1) < T;
        if (more) {
            const int off = (t + 1) * 32;
            cpasync16(nsBase + 2 * OPSZ + aStOff,      Bhp + off);
            cpasync16(nsBase + 2 * OPSZ + aStOff + 16, Bhp + off + 8);
            cpasync16(nsBase + 3 * OPSZ + aStOff,      Blp + off);
            cpasync16(nsBase + 3 * OPSZ + aStOff + 16, Blp + off + 8);
            cp_commit();
#pragma unroll
            for (int i = 0; i < 4; i++) ar[i] = *(const float4*)(Ap + off + 4 * i);
        }

#pragma unroll
        for (int ks = 0; ks < 2; ks++) {
            const uint32_t kb = ks * 32;
            uint32_t Ah[2][4], Al[2][4];
#pragma unroll
            for (int mf = 0; mf < 2; mf++) {
                ldmx4(Ah[mf], sA + aOff + mf * (16 * ROWB) + kb);
                ldmx4(Al[mf], sA + OPSZ + aOff + mf * (16 * ROWB) + kb);
            }
#pragma unroll
            for (int qh = 0; qh < 2; qh++) {
                uint32_t Bh2[2][4], Bl2[2][4];
#pragma unroll
                for (int qq = 0; qq < 2; qq++) {
                    const int q = qh * 2 + qq;
                    ldmx4(Bh2[qq], sA + 2 * OPSZ + bOff + q * (16 * ROWB) + kb);
                    ldmx4(Bl2[qq], sA + 3 * OPSZ + bOff + q * (16 * ROWB) + kb);
                }
#pragma unroll
                for (int mf = 0; mf < 2; mf++)
#pragma unroll
                    for (int qq = 0; qq < 2; qq++)
#pragma unroll
                        for (int j = 0; j < 2; j++) {
                            const int nf = qh * 4 + qq * 2 + j;
                            const int rr = j * 2;
                            mma_bf16(acc[mf][nf], Ah[mf], Bh2[qq][rr], Bh2[qq][rr + 1]);
                            mma_bf16(acc[mf][nf], Ah[mf], Bl2[qq][rr], Bl2[qq][rr + 1]);
                            mma_bf16(acc[mf][nf], Al[mf], Bh2[qq][rr], Bh2[qq][rr + 1]);
                        }
            }
        }

        if (more) {
            char* other = smem + (s ^ 1) * STGSZ;
            char* sAh = other + aStOff;
            char* sAl = other + OPSZ + aStOff;
#pragma unroll
            for (int i = 0; i < 4; i++) {
                float4 v = ar[i];
                __nv_bfloat162 h01 = __floats2bfloat162_rn(v.x, v.y);
                __nv_bfloat162 h23 = __floats2bfloat162_rn(v.z, v.w);
                __nv_bfloat162 l01 = __floats2bfloat162_rn(v.x - __low2float(h01), v.y - __high2float(h01));
                __nv_bfloat162 l23 = __floats2bfloat162_rn(v.z - __low2float(h23), v.w - __high2float(h23));
                *(uint2*)(sAh + 8 * i) = make_uint2(*(uint32_t*)&h01, *(uint32_t*)&h23);
                *(uint2*)(sAl + 8 * i) = make_uint2(*(uint32_t*)&l01, *(uint32_t*)&l23);
            }
        }
    }

    float* outb = g_LxP + (size_t)ksl * (MTOT * DIM);
    const int g = lane >> 2, t4 = lane & 3;
#pragma unroll
    for (int mf = 0; mf < 2; mf++) {
        const int row0 = m0 + wm * 32 + mf * 16 + g;
#pragma unroll
        for (int nf = 0; nf < 8; nf++) {
            const int col = wn * 64 + nf * 8 + t4 * 2;
            *(float2*)(outb + (size_t)row0 * DIM + col) =
                make_float2(acc[mf][nf][0], acc[mf][nf][1]);
            *(float2*)(outb + (size_t)(row0 + 8) * DIM + col) =
                make_float2(acc[mf][nf][2], acc[mf][nf][3]);
        }
    }
}

// ---------------- BN stats pass 1 + K-split fold ----------------------------
__global__ __launch_bounds__(256) void stats_partial(int xsel) {
    const float* __restrict__ X = xsel ? g_bufX2 : g_bufX;
    const int tid = threadIdx.x;
    const int c = tid & 127;
    const int half = tid >> 7;
    const int rpb = MTOT / STATS_BLOCKS;   // 16
    const int r0 = blockIdx.x * rpb;

    float sx = 0.f, sxx = 0.f, sl = 0.f, sll = 0.f;
#pragma unroll 4
    for (int r = r0 + half; r < r0 + rpb; r += 2) {
        float v = X[r * DIM + c];
        sx += v; sxx += v * v;
        size_t idx = (size_t)r * DIM + c;
        float w = 0.f;
#pragma unroll
        for (int q = 0; q < NKSL; q++) w += g_LxP[idx + (size_t)q * MTOT * DIM];
        g_LxP[idx] = w;
        sl += w; sll += w * w;
    }
    __shared__ float sh[256];
    const int b = blockIdx.x;
    sh[tid] = sx;  __syncthreads();
    if (tid < 128) g_partials[(0 * 128 + c) * STATS_BLOCKS + b] = sh[tid] + sh[tid + 128];
    __syncthreads();
    sh[tid] = sxx; __syncthreads();
    if (tid < 128) g_partials[(1 * 128 + c) * STATS_BLOCKS + b] = sh[tid] + sh[tid + 128];
    __syncthreads();
    sh[tid] = sl;  __syncthreads();
    if (tid < 128) g_partials[(2 * 128 + c) * STATS_BLOCKS + b] = sh[tid] + sh[tid + 128];
    __syncthreads();
    sh[tid] = sll; __syncthreads();
    if (tid < 128) g_partials[(3 * 128 + c) * STATS_BLOCKS + b] = sh[tid] + sh[tid + 128];
}

// ---------------- BN stats pass 2: float4 reads -----------------------------
__global__ __launch_bounds__(256) void stats_final(const float* __restrict__ gamma,
                                                   const float* __restrict__ beta) {
    const int warp = threadIdx.x >> 5;
    const int lane = threadIdx.x & 31;
    const int k = blockIdx.x * 8 + warp;
    const int base = (k < 128) ? 0 : 2;
    const int c = k & 127;
    const float4* ps = (const float4*)(g_partials + (size_t)(base * 128 + c) * STATS_BLOCKS);
    const float4* pq = (const float4*)(g_partials + (size_t)((base + 1) * 128 + c) * STATS_BLOCKS);
    float s = 0.f, ss = 0.f;
#pragma unroll
    for (int i = 0; i < STATS_BLOCKS / 128; i++) {   // 4
        float4 a = ps[lane + 32 * i];
        float4 b = pq[lane + 32 * i];
        s  += (a.x + a.y) + (a.z + a.w);
        ss += (b.x + b.y) + (b.z + b.w);
    }
    s = warp_sum(s);
    ss = warp_sum(ss);
    if (lane == 0) {
        float mean = s / (float)MTOT;
        float var  = ss / (float)MTOT - mean * mean;
        float sc   = rsqrtf(var + EPSV) * gamma[k];
        g_scale[k] = sc;
        g_shift[k] = beta[k] - mean * sc;
    }
}

// ---------------- fold BN into linear weights: bf16 split + beff ------------
__global__ __launch_bounds__(256) void weff_kernel(const float* __restrict__ w,
                                                   const float* __restrict__ b) {
    const int e0 = (blockIdx.x * 256 + threadIdx.x) * 4;
    const int j = e0 >> 8;
    const int k0 = e0 & 255;
    float4 wv = *(const float4*)(w + j * 256 + k0);
    float4 sv = *(const float4*)(g_scale + k0);
    float p0 = wv.x * sv.x, p1 = wv.y * sv.y, p2 = wv.z * sv.z, p3 = wv.w * sv.w;
    __nv_bfloat162 h01 = __floats2bfloat162_rn(p0, p1);
    __nv_bfloat162 h23 = __floats2bfloat162_rn(p2, p3);
    __nv_bfloat162 l01 = __floats2bfloat162_rn(p0 - __low2float(h01), p1 - __high2float(h01));
    __nv_bfloat162 l23 = __floats2bfloat162_rn(p2 - __low2float(h23), p3 - __high2float(h23));
    *(uint2*)(g_wBh + j * 256 + k0) = make_uint2(*(uint32_t*)&h01, *(uint32_t*)&h23);
    *(uint2*)(g_wBl + j * 256 + k0) = make_uint2(*(uint32_t*)&l01, *(uint32_t*)&l23);

    if (blockIdx.x < 16) {
        const int warp = threadIdx.x >> 5;
        const int lane = threadIdx.x & 31;
        const int jo = blockIdx.x * 8 + warp;
        const float4* wj = (const float4*)(w + jo * 256);
        const float4* sh4 = (const float4*)g_shift;
        float s = 0.f;
#pragma unroll
        for (int i = 0; i < 2; i++) {
            float4 a = wj[lane + 32 * i];
            float4 c4 = sh4[lane + 32 * i];
            s += a.x * c4.x + a.y * c4.y + a.z * c4.z + a.w * c4.w;
        }
        s = warp_sum(s);
        if (lane == 0) g_beff[jo] = b[jo] + s;
    }
}

// ---------------- HMMA linear: M=64 tiles, 128 CTAs -------------------------
// out = [X|Lx] @ w'^T + beff; mode 0: elu->g_bufX2 + pack B; mode 1: +resid->dst
#define L_AOP 5120                       // A operand: 64 rows x 80 B
#define L_BBASE (2 * L_AOP)              // 10240
#define L_STG (2 * L_AOP + 2 * OPSZ)     // 30720
#define LIN_SMEM (2 * L_STG)             // 61440

__global__ __launch_bounds__(256, 2) void linear_mma(int xsel,
                                                     const float* __restrict__ resid,
                                                     float* __restrict__ dst, int mode) {
    extern __shared__ char smem[];
    const int tid = threadIdx.x;
    const int lane = tid & 31;
    const int w = tid >> 5;
    const int wm = w >> 1;                 // 0..3 : 16-row band
    const int wn = w & 1;                  // 0..1 : 64-col band
    const int m0 = blockIdx.x * 64;

    const uint32_t sb = smem_u32(smem);
    const float* __restrict__ Xs = xsel ? g_bufX2 : g_bufX;

    const int a_row = wm * 16 + (lane & 7) + ((lane >> 3) & 1) * 8;
    const uint32_t aOff = (uint32_t)a_row * ROWB + ((lane >> 4) & 1) * 16;
    const int b_row = wn * 64 + (lane & 7) + ((lane >> 4) & 1) * 8;
    const uint32_t bOff = (uint32_t)b_row * ROWB + ((lane >> 3) & 1) * 16;

    // A global: row = tid>>2 (0..63), seg = (tid&3)*8 cols
    const int garow = tid >> 2;
    const int gseg = tid & 3;
    const uint32_t aStOff = (uint32_t)garow * ROWB + gseg * 16;
    // B global: row = tid>>1 (0..127 of w'), half = tid&1
    const int gbrow = tid >> 1;
    const int gbh = tid & 1;
    const __nv_bfloat16* Bhp = g_wBh + (size_t)gbrow * FEAT + gbh * 16;
    const __nv_bfloat16* Blp = g_wBl + (size_t)gbrow * FEAT + gbh * 16;
    const uint32_t bStOff = (uint32_t)gbrow * ROWB + gbh * 32;

    float acc[8][4];
#pragma unroll
    for (int j = 0; j < 8; j++)
#pragma unroll
        for (int q = 0; q < 4; q++) acc[j][q] = 0.f;

    float4 ar[2];

    auto aPtr = [&](int t) -> const float* {
        int kk = t * 32 + gseg * 8;
        return (kk < 128) ? (Xs + (size_t)(m0 + garow) * DIM + kk)
                          : (g_LxP + (size_t)(m0 + garow) * DIM + (kk - 128));
    };
    auto convA = [&](char* base, float4* v) {
        char* sAh = base + aStOff;
        char* sAl = base + L_AOP + aStOff;
#pragma unroll
        for (int i = 0; i < 2; i++) {
            float4 x = v[i];
            __nv_bfloat162 h01 = __floats2bfloat162_rn(x.x, x.y);
            __nv_bfloat162 h23 = __floats2bfloat162_rn(x.z, x.w);
            __nv_bfloat162 l01 = __floats2bfloat162_rn(x.x - __low2float(h01), x.y - __high2float(h01));
            __nv_bfloat162 l23 = __floats2bfloat162_rn(x.z - __low2float(h23), x.w - __high2float(h23));
            *(uint2*)(sAh + 8 * i) = make_uint2(*(uint32_t*)&h01, *(uint32_t*)&h23);
            *(uint2*)(sAl + 8 * i) = make_uint2(*(uint32_t*)&l01, *(uint32_t*)&l23);
        }
    };

    cpasync16(sb + L_BBASE + bStOff,              Bhp);
    cpasync16(sb + L_BBASE + bStOff + 16,         Bhp + 8);
    cpasync16(sb + L_BBASE + OPSZ + bStOff,       Blp);
    cpasync16(sb + L_BBASE + OPSZ + bStOff + 16,  Blp + 8);
    cp_commit();
    {
        const float* ap = aPtr(0);
        ar[0] = *(const float4*)ap;
        ar[1] = *(const float4*)(ap + 4);
        convA(smem, ar);
    }

    const int T = FEAT / 32;  // 8

    for (int t = 0; t < T; t++) {
        cp_wait0();
        __syncthreads();
        const int s = t & 1;
        const uint32_t sA = sb + s * L_STG;
        const uint32_t nsBase = sb + (s ^ 1) * L_STG;
        const bool more = (t + 1) < T;
        if (more) {
            const int off = (t + 1) * 32;
            cpasync16(nsBase + L_BBASE + bStOff,              Bhp + off);
            cpasync16(nsBase + L_BBASE + bStOff + 16,         Bhp + off + 8);
            cpasync16(nsBase + L_BBASE + OPSZ + bStOff,       Blp + off);
            cpasync16(nsBase + L_BBASE + OPSZ + bStOff + 16,  Blp + off + 8);
            cp_commit();
            const float* ap = aPtr(t + 1);
            ar[0] = *(const float4*)ap;
            ar[1] = *(const float4*)(ap + 4);
        }

#pragma unroll
        for (int ks = 0; ks < 2; ks++) {
            const uint32_t kb = ks * 32;
            uint32_t Ah[4], Al[4];
            ldmx4(Ah, sA + aOff + kb);
            ldmx4(Al, sA + L_AOP + aOff + kb);
#pragma unroll
            for (int qh = 0; qh < 2; qh++) {
                uint32_t Bh2[2][4], Bl2[2][4];
#pragma unroll
                for (int qq = 0; qq < 2; qq++) {
                    const int q = qh * 2 + qq;
                    ldmx4(Bh2[qq], sA + L_BBASE + bOff + q * (16 * ROWB) + kb);
                    ldmx4(Bl2[qq], sA + L_BBASE + OPSZ + bOff + q * (16 * ROWB) + kb);
                }
#pragma unroll
                for (int qq = 0; qq < 2; qq++)
#pragma unroll
                    for (int j = 0; j < 2; j++) {
                        const int nf = qh * 4 + qq * 2 + j;
                        const int rr = j * 2;
                        mma_bf16(acc[nf], Ah, Bh2[qq][rr], Bh2[qq][rr + 1]);
                        mma_bf16(acc[nf], Ah, Bl2[qq][rr], Bl2[qq][rr + 1]);
                        mma_bf16(acc[nf], Al, Bh2[qq][rr], Bh2[qq][rr + 1]);
                    }
            }
        }

        if (more) {
            convA(smem + (s ^ 1) * L_STG, ar);
        }
    }

    const int g = lane >> 2, t4 = lane & 3;
    const int row0 = m0 + wm * 16 + g;
#pragma unroll
    for (int nf = 0; nf < 8; nf++) {
        const int col = wn * 64 + nf * 8 + t4 * 2;
        float b0 = g_beff[col], b1 = g_beff[col + 1];
        float y0 = acc[nf][0] + b0;
        float y1 = acc[nf][1] + b1;
        float y2 = acc[nf][2] + b0;
        float y3 = acc[nf][3] + b1;
        if (mode == 0) {
            float v0 = eluf(y0), v1 = eluf(y1), v2 = eluf(y2), v3 = eluf(y3);
            *(float2*)(g_bufX2 + (size_t)row0 * DIM + col) = make_float2(v0, v1);
            *(float2*)(g_bufX2 + (size_t)(row0 + 8) * DIM + col) = make_float2(v2, v3);
            __nv_bfloat16 h, l;
            split_bf16(v0, h, l);
            g_Bh[(size_t)col * MTOT + row0] = h;       g_Bl[(size_t)col * MTOT + row0] = l;
            split_bf16(v1, h, l);
            g_Bh[(size_t)(col + 1) * MTOT + row0] = h; g_Bl[(size_t)(col + 1) * MTOT + row0] = l;
            split_bf16(v2, h, l);
            g_Bh[(size_t)col * MTOT + row0 + 8] = h;       g_Bl[(size_t)col * MTOT + row0 + 8] = l;
            split_bf16(v3, h, l);
            g_Bh[(size_t)(col + 1) * MTOT + row0 + 8] = h; g_Bl[(size_t)(col + 1) * MTOT + row0 + 8] = l;
        } else {
            float r0v = resid[(size_t)row0 * DIM + col];
            float r1v = resid[(size_t)row0 * DIM + col + 1];
            float r2v = resid[(size_t)(row0 + 8) * DIM + col];
            float r3v = resid[(size_t)(row0 + 8) * DIM + col + 1];
            *(float2*)(dst + (size_t)row0 * DIM + col) = make_float2(y0 + r0v, y1 + r1v);
            *(float2*)(dst + (size_t)(row0 + 8) * DIM + col) = make_float2(y2 + r2v, y3 + r3v);
        }
    }
}

// ---------------- launch ----------------------------------------------------
extern "C" void kernel_launch(void* const* d_in, const int* in_sizes, int n_in,
                              void* d_out, int out_size) {
    const float* L      = (const float*)d_in[0];
    const float* inputs = (const float*)d_in[2];
    const float* bn0_g  = (const float*)d_in[3];
    const float* bn0_b  = (const float*)d_in[4];
    const float* fc0_w  = (const float*)d_in[5];
    const float* fc0_b  = (const float*)d_in[6];
    const float* bn1_g  = (const float*)d_in[7];
    const float* bn1_b  = (const float*)d_in[8];
    const float* fc1_w  = (const float*)d_in[9];
    const float* fc1_b  = (const float*)d_in[10];
    float* out = (float*)d_out;

    cudaFuncSetAttribute(sgemm_mma, cudaFuncAttributeMaxDynamicSharedMemorySize, SGEMM_SMEM);
    cudaFuncSetAttribute(linear_mma, cudaFuncAttributeMaxDynamicSharedMemorySize, LIN_SMEM);

    // ---- block 0 ----
    pack_kernel<<<128, 256>>>(inputs);
    sgemm_mma<<<512, 256, SGEMM_SMEM>>>(L);
    stats_partial<<<STATS_BLOCKS, 256>>>(0);
    stats_final<<<32, 256>>>(bn0_g, bn0_b);
    weff_kernel<<<32, 256>>>(fc0_w, fc0_b);
    linear_mma<<<128, 256, LIN_SMEM>>>(0, nullptr, nullptr, 0);  // also packs B for block 1

    // ---- block 1 ----
    sgemm_mma<<<512, 256, SGEMM_SMEM>>>(L);
    stats_partial<<<STATS_BLOCKS, 256>>>(1);
    stats_final<<<32, 256>>>(bn1_g, bn1_b);
    weff_kernel<<<32, 256>>>(fc1_w, fc1_b);
    linear_mma<<<128, 256, LIN_SMEM>>>(1, inputs, out, 1);
}